// round 14
// baseline (speedup 1.0000x reference)
#include <cuda_runtime.h>
#include <cuda_bf16.h>
#include <stdint.h>
#include <math.h>

#define Cdim 192
#define Dn 8
#define Hn 32
#define Wn 32
#define NHEAD 6
#define HDIM 32
#define HIDN 768
#define NTOK 8192
#define SCALE 0.17677669529663687f

typedef __nv_bfloat16 bf16;

// ---------------- scratch ----------------
__device__ float g_t[NTOK * Cdim];
__device__ float g_xt[Cdim * Dn * Hn * Wn];
__device__ float g_s[NTOK * Cdim];
__device__ bf16  g_qkvb[NTOK * 3 * Cdim];
__device__ bf16  g_yb[NTOK * Cdim];
__device__ bf16  g_ob[NTOK * Cdim];
__device__ bf16  g_wb[884736];

#define OFF_TQKV 0
#define OFF_TOUT 110592
#define OFF_TFC1 147456
#define OFF_TFC2 294912
#define OFF_SQKV 442368
#define OFF_SPROJ 552960
#define OFF_SFC1 589824
#define OFF_SFC2 737280

__device__ __forceinline__ float warp_sum(float v) {
#pragma unroll
    for (int o = 16; o > 0; o >>= 1) v += __shfl_xor_sync(0xffffffffu, v, o);
    return v;
}

__device__ __forceinline__ void cp16(void* dst, const void* src) {
    unsigned d = (unsigned)__cvta_generic_to_shared(dst);
    asm volatile("cp.async.cg.shared.global [%0], [%1], 16;" :: "r"(d), "l"(src));
}

__device__ __forceinline__ float gelu_f(float v) {
    return 0.5f * v * (1.0f + erff(v * 0.7071067811865476f));
}

__device__ __forceinline__ void pdl_sync() { cudaGridDependencySynchronize(); }
__device__ __forceinline__ void pdl_trig() { cudaTriggerProgrammaticLaunchCompletion(); }

// ---------------- kernel 1: convert weights + build t + LN1 (merged) -----------
__global__ void convert_build_kernel(
    const float* __restrict__ x, const float* __restrict__ pe,
    const float* __restrict__ g, const float* __restrict__ b,
    const float* __restrict__ a0, const float* __restrict__ a1,
    const float* __restrict__ a2, const float* __restrict__ a3,
    const float* __restrict__ a4, const float* __restrict__ a5,
    const float* __restrict__ a6, const float* __restrict__ a7) {
    int blk = blockIdx.x;
    int tid = threadIdx.x;
    if (blk >= 256) {
        int i = (blk - 256) * 256 + tid;
        const float* src; int off;
        if      (i < 110592) { src = a0; off = 0; }
        else if (i < 147456) { src = a1; off = 110592; }
        else if (i < 294912) { src = a2; off = 147456; }
        else if (i < 442368) { src = a3; off = 294912; }
        else if (i < 552960) { src = a4; off = 442368; }
        else if (i < 589824) { src = a5; off = 552960; }
        else if (i < 737280) { src = a6; off = 589824; }
        else                 { src = a7; off = 737280; }
        g_wb[i] = __float2bfloat16(src[i - off]);
        pdl_trig();
        return;
    }
    __shared__ float xsm[Cdim][33];
    int s = blk >> 5;
    int hw0 = (blk & 31) * 32;
    int tx = tid & 31, ty = tid >> 5;
    int warp = ty, lane = tx;

#pragma unroll
    for (int i = 0; i < 24; i++) {
        int c = ty + 8 * i;
        xsm[c][tx] = x[((size_t)c * 8 + s) * 1024 + hw0 + tx] + pe[s * Cdim + c];
    }
    __syncthreads();

#pragma unroll
    for (int i = 0; i < 4; i++) {
        int hwl = warp + 8 * i;
        size_t r = (size_t)(hw0 + hwl) * 8 + s;
        float v[6];
        float sum = 0.f;
#pragma unroll
        for (int j = 0; j < 6; j++) { v[j] = xsm[lane + 32 * j][hwl]; sum += v[j]; }
        sum = warp_sum(sum);
        float m = sum * (1.0f / Cdim);
        float var = 0.f;
#pragma unroll
        for (int j = 0; j < 6; j++) { float d = v[j] - m; var += d * d; }
        var = warp_sum(var) * (1.0f / Cdim);
        float rstd = rsqrtf(var + 1e-5f);
#pragma unroll
        for (int j = 0; j < 6; j++) {
            int c = lane + 32 * j;
            g_t[r * Cdim + c] = v[j];
            g_yb[r * Cdim + c] = __float2bfloat16((v[j] - m) * rstd * g[c] + b[c]);
        }
    }
    pdl_trig();
}

// ---------------- fused: y = LNf(t); xt = x + y^T; s-stream + s_ln1 ------------
__global__ void lnf_add_kernel(const float* __restrict__ x,
                               const float* __restrict__ g, const float* __restrict__ b,
                               const float* __restrict__ g2, const float* __restrict__ b2) {
    pdl_sync();
    __shared__ float vsm[Cdim][33];
    int s = blockIdx.x;
    int hw0 = blockIdx.y * 32;
    int tx = threadIdx.x, ty = threadIdx.y;
    int tid = ty * 32 + tx;
    int warp = tid >> 5, lane = tid & 31;

#pragma unroll
    for (int i = 0; i < 4; i++) {
        int hwl = warp + 8 * i;
        size_t r = (size_t)(hw0 + hwl) * 8 + s;
        float v[6];
        float sum = 0.f;
#pragma unroll
        for (int j = 0; j < 6; j++) { v[j] = g_t[r * Cdim + lane + 32 * j]; sum += v[j]; }
        sum = warp_sum(sum);
        float m = sum * (1.0f / Cdim);
        float var = 0.f;
#pragma unroll
        for (int j = 0; j < 6; j++) { float d = v[j] - m; var += d * d; }
        var = warp_sum(var) * (1.0f / Cdim);
        float rstd = rsqrtf(var + 1e-5f);
#pragma unroll
        for (int j = 0; j < 6; j++) {
            int c = lane + 32 * j;
            vsm[c][hwl] = (v[j] - m) * rstd * g[c] + b[c];
        }
    }
    __syncthreads();

#pragma unroll
    for (int i = 0; i < 24; i++) {
        int c = ty + 8 * i;
        size_t xi = ((size_t)c * 8 + s) * 1024 + hw0 + tx;
        float val = x[xi] + vsm[c][tx];
        g_xt[xi] = val;
        vsm[c][tx] = val;
    }
    __syncthreads();

#pragma unroll
    for (int i = 0; i < 4; i++) {
        int hwl = warp + 8 * i;
        size_t r = (size_t)s * 1024 + hw0 + hwl;
        float v[6];
        float sum = 0.f;
#pragma unroll
        for (int j = 0; j < 6; j++) { v[j] = vsm[lane + 32 * j][hwl]; sum += v[j]; }
        sum = warp_sum(sum);
        float m = sum * (1.0f / Cdim);
        float var = 0.f;
#pragma unroll
        for (int j = 0; j < 6; j++) { float d = v[j] - m; var += d * d; }
        var = warp_sum(var) * (1.0f / Cdim);
        float rstd = rsqrtf(var + 1e-5f);
#pragma unroll
        for (int j = 0; j < 6; j++) {
            int c = lane + 32 * j;
            g_s[r * Cdim + c] = v[j];
            g_yb[r * Cdim + c] = __float2bfloat16((v[j] - m) * rstd * g2[c] + b2[c]);
        }
    }
    pdl_trig();
}

#define AST 40
#define BST 72

// ============ wide GEMM: BM=128, BN=64, BK=32, 3-stage ring (qkv) ============
#define A_TILE (128 * AST)
#define B_TILE (32 * BST)
__global__ __launch_bounds__(256) void gemm_bf16(
    const bf16* __restrict__ A, const bf16* __restrict__ B,
    const float* __restrict__ bias, bf16* __restrict__ outb,
    int M, int N, int K) {
    pdl_sync();
    __shared__ bf16 As[3][A_TILE];
    __shared__ bf16 Bs[3][B_TILE];
    const int tid = threadIdx.x;
    const int lane = tid & 31;
    const int wid = tid >> 5;
    const int wm = wid >> 1, wn = wid & 1;
    const int row0 = blockIdx.y * 128, col0 = blockIdx.x * 64;
    const int gq = lane >> 2, tq = lane & 3;

    const int lrow8 = (lane & 7) + 8 * ((lane >> 3) & 1);
    const int lcol8 = 8 * (lane >> 4);
    unsigned as_base = (unsigned)__cvta_generic_to_shared(&As[0][0]);
    unsigned bs_base = (unsigned)__cvta_generic_to_shared(&Bs[0][0]);

    float acc[2][4][4] = {};

    const int a_m = (tid >> 2), a_q = (tid & 3);
    const int b_k = (tid >> 3), b_q = (tid & 7);

    auto load_tile = [&](int buf, int k0) {
#pragma unroll
        for (int j = 0; j < 2; j++) {
            int m = a_m + j * 64;
            cp16(&As[buf][m * AST + a_q * 8], &A[(size_t)(row0 + m) * K + k0 + a_q * 8]);
        }
        cp16(&Bs[buf][b_k * BST + b_q * 8], &B[(size_t)(k0 + b_k) * N + col0 + b_q * 8]);
        asm volatile("cp.async.commit_group;");
    };

    unsigned af[2][2][4], bfr[2][4][2];
    auto load_frag = [&](int pb, unsigned abuf, unsigned bbuf, int ks) {
#pragma unroll
        for (int i = 0; i < 2; i++) {
            unsigned addr = abuf + (unsigned)(((wm * 32 + i * 16 + lrow8) * AST + ks + lcol8) * 2);
            asm volatile("ldmatrix.sync.aligned.m8n8.x4.shared.b16 {%0,%1,%2,%3}, [%4];"
                         : "=r"(af[pb][i][0]), "=r"(af[pb][i][1]),
                           "=r"(af[pb][i][2]), "=r"(af[pb][i][3])
                         : "r"(addr));
        }
#pragma unroll
        for (int jp = 0; jp < 2; jp++) {
            unsigned addr = bbuf + (unsigned)(((ks + lrow8) * BST + wn * 32 + jp * 16 + lcol8) * 2);
            asm volatile("ldmatrix.sync.aligned.m8n8.x4.trans.shared.b16 {%0,%1,%2,%3}, [%4];"
                         : "=r"(bfr[pb][jp * 2][0]), "=r"(bfr[pb][jp * 2][1]),
                           "=r"(bfr[pb][jp * 2 + 1][0]), "=r"(bfr[pb][jp * 2 + 1][1])
                         : "r"(addr));
        }
    };

    const int nk = K / 32;
    load_tile(0, 0);
    if (nk > 1) load_tile(1, 32);

    for (int it = 0; it < nk; it++) {
        if (it + 1 < nk) asm volatile("cp.async.wait_group 1;");
        else             asm volatile("cp.async.wait_group 0;");
        __syncthreads();
        if (it + 2 < nk) load_tile((it + 2) % 3, (it + 2) * 32);

        int buf = it % 3;
        unsigned abuf = as_base + buf * (A_TILE * 2);
        unsigned bbuf = bs_base + buf * (B_TILE * 2);
        load_frag(0, abuf, bbuf, 0);
#pragma unroll
        for (int ks = 0; ks < 2; ks++) {
            int pb = ks & 1;
            if (ks < 1) load_frag(pb ^ 1, abuf, bbuf, 16);
#pragma unroll
            for (int i = 0; i < 2; i++)
#pragma unroll
                for (int j = 0; j < 4; j++) {
                    asm volatile(
                        "mma.sync.aligned.m16n8k16.row.col.f32.bf16.bf16.f32 "
                        "{%0,%1,%2,%3}, {%4,%5,%6,%7}, {%8,%9}, {%0,%1,%2,%3};"
                        : "+f"(acc[i][j][0]), "+f"(acc[i][j][1]),
                          "+f"(acc[i][j][2]), "+f"(acc[i][j][3])
                        : "r"(af[pb][i][0]), "r"(af[pb][i][1]),
                          "r"(af[pb][i][2]), "r"(af[pb][i][3]),
                          "r"(bfr[pb][j][0]), "r"(bfr[pb][j][1]));
                }
        }
    }
    pdl_trig();

#pragma unroll
    for (int i = 0; i < 2; i++) {
        int r = row0 + wm * 32 + i * 16 + gq;
#pragma unroll
        for (int j = 0; j < 4; j++) {
            int c = col0 + wn * 32 + j * 8 + 2 * tq;
            float v0 = acc[i][j][0], v1 = acc[i][j][1];
            float v2 = acc[i][j][2], v3 = acc[i][j][3];
            if (bias) {
                float b0 = bias[c], b1 = bias[c + 1];
                v0 += b0; v1 += b1; v2 += b0; v3 += b1;
            }
            outb[(size_t)r * N + c]           = __float2bfloat16(v0);
            outb[(size_t)r * N + c + 1]       = __float2bfloat16(v1);
            outb[(size_t)(r + 8) * N + c]     = __float2bfloat16(v2);
            outb[(size_t)(r + 8) * N + c + 1] = __float2bfloat16(v3);
        }
    }
}

// ============ fused GEMM+LN: BM=64, BN=192 (proj + ln2) ============
#define ASTL 40
#define BSTL 200
#define A_TILE_L (64 * ASTL)
#define B_TILE_L (32 * BSTL)
__global__ __launch_bounds__(256) void gemm_ln(
    const bf16* __restrict__ A, const bf16* __restrict__ B,
    const float* __restrict__ bias, const float* __restrict__ res,
    float* __restrict__ outres, bf16* __restrict__ outln,
    const float* __restrict__ lng, const float* __restrict__ lnb,
    int K) {
    pdl_sync();
    extern __shared__ char smraw[];
    bf16* As = (bf16*)smraw;
    bf16* Bs = (bf16*)smraw + 3 * A_TILE_L;
    float* epi = (float*)smraw;
    const int tid = threadIdx.x;
    const int lane = tid & 31;
    const int wid = tid >> 5;
    const int wm = wid >> 2, wn = wid & 3;
    const int row0 = blockIdx.x * 64;
    const int gq = lane >> 2, tq = lane & 3;

    const int lrow8 = (lane & 7) + 8 * ((lane >> 3) & 1);
    const int lcol8 = 8 * (lane >> 4);
    unsigned as_base = (unsigned)__cvta_generic_to_shared(As);
    unsigned bs_base = (unsigned)__cvta_generic_to_shared(Bs);

    float acc[2][6][4] = {};

    const int a_m = tid >> 2, a_q = tid & 3;
    const int b_k = tid >> 3, b_q = tid & 7;

    auto load_tile = [&](int buf, int k0) {
        cp16(&As[buf * A_TILE_L + a_m * ASTL + a_q * 8],
             &A[(size_t)(row0 + a_m) * K + k0 + a_q * 8]);
#pragma unroll
        for (int p = 0; p < 3; p++) {
            int cc = b_q * 8 + p * 64;
            cp16(&Bs[buf * B_TILE_L + b_k * BSTL + cc],
                 &B[(size_t)(k0 + b_k) * Cdim + cc]);
        }
        asm volatile("cp.async.commit_group;");
    };

    unsigned af[2][2][4], bfr[2][6][2];
    auto load_frag = [&](int pb, unsigned abuf, unsigned bbuf, int ks) {
#pragma unroll
        for (int i = 0; i < 2; i++) {
            unsigned addr = abuf + (unsigned)(((wm * 32 + i * 16 + lrow8) * ASTL + ks + lcol8) * 2);
            asm volatile("ldmatrix.sync.aligned.m8n8.x4.shared.b16 {%0,%1,%2,%3}, [%4];"
                         : "=r"(af[pb][i][0]), "=r"(af[pb][i][1]),
                           "=r"(af[pb][i][2]), "=r"(af[pb][i][3])
                         : "r"(addr));
        }
#pragma unroll
        for (int jp = 0; jp < 3; jp++) {
            unsigned addr = bbuf + (unsigned)(((ks + lrow8) * BSTL + wn * 48 + jp * 16 + lcol8) * 2);
            asm volatile("ldmatrix.sync.aligned.m8n8.x4.trans.shared.b16 {%0,%1,%2,%3}, [%4];"
                         : "=r"(bfr[pb][jp * 2][0]), "=r"(bfr[pb][jp * 2][1]),
                           "=r"(bfr[pb][jp * 2 + 1][0]), "=r"(bfr[pb][jp * 2 + 1][1])
                         : "r"(addr));
        }
    };

    const int nk = K / 32;
    load_tile(0, 0);
    if (nk > 1) load_tile(1, 32);

    for (int it = 0; it < nk; it++) {
        if (it + 1 < nk) asm volatile("cp.async.wait_group 1;");
        else             asm volatile("cp.async.wait_group 0;");
        __syncthreads();
        if (it + 2 < nk) load_tile((it + 2) % 3, (it + 2) * 32);

        int buf = it % 3;
        unsigned abuf = as_base + buf * (A_TILE_L * 2);
        unsigned bbuf = bs_base + buf * (B_TILE_L * 2);
        load_frag(0, abuf, bbuf, 0);
#pragma unroll
        for (int ks = 0; ks < 2; ks++) {
            int pb = ks & 1;
            if (ks < 1) load_frag(pb ^ 1, abuf, bbuf, 16);
#pragma unroll
            for (int i = 0; i < 2; i++)
#pragma unroll
                for (int j = 0; j < 6; j++) {
                    asm volatile(
                        "mma.sync.aligned.m16n8k16.row.col.f32.bf16.bf16.f32 "
                        "{%0,%1,%2,%3}, {%4,%5,%6,%7}, {%8,%9}, {%0,%1,%2,%3};"
                        : "+f"(acc[i][j][0]), "+f"(acc[i][j][1]),
                          "+f"(acc[i][j][2]), "+f"(acc[i][j][3])
                        : "r"(af[pb][i][0]), "r"(af[pb][i][1]),
                          "r"(af[pb][i][2]), "r"(af[pb][i][3]),
                          "r"(bfr[pb][j][0]), "r"(bfr[pb][j][1]));
                }
        }
    }
    pdl_trig();
    __syncthreads();

#pragma unroll
    for (int i = 0; i < 2; i++) {
        int rl = wm * 32 + i * 16 + gq;
        size_t r = (size_t)(row0 + rl);
#pragma unroll
        for (int j = 0; j < 6; j++) {
            int c = wn * 48 + j * 8 + 2 * tq;
            float v0 = acc[i][j][0] + bias[c]     + res[r * Cdim + c];
            float v1 = acc[i][j][1] + bias[c + 1] + res[r * Cdim + c + 1];
            float v2 = acc[i][j][2] + bias[c]     + res[(r + 8) * Cdim + c];
            float v3 = acc[i][j][3] + bias[c + 1] + res[(r + 8) * Cdim + c + 1];
            epi[rl * 193 + c]           = v0;
            epi[rl * 193 + c + 1]       = v1;
            epi[(rl + 8) * 193 + c]     = v2;
            epi[(rl + 8) * 193 + c + 1] = v3;
        }
    }
    __syncthreads();

#pragma unroll
    for (int rr = 0; rr < 8; rr++) {
        int rl = wid * 8 + rr;
        size_t r = (size_t)(row0 + rl);
        float v[6];
        float sum = 0.f;
#pragma unroll
        for (int j = 0; j < 6; j++) { v[j] = epi[rl * 193 + lane + 32 * j]; sum += v[j]; }
        sum = warp_sum(sum);
        float m = sum * (1.0f / Cdim);
        float var = 0.f;
#pragma unroll
        for (int j = 0; j < 6; j++) { float d = v[j] - m; var += d * d; }
        var = warp_sum(var) * (1.0f / Cdim);
        float rstd = rsqrtf(var + 1e-5f);
#pragma unroll
        for (int j = 0; j < 6; j++) {
            int c = lane + 32 * j;
            outres[r * Cdim + c] = v[j];
            outln[r * Cdim + c] = __float2bfloat16((v[j] - m) * rstd * lng[c] + lnb[c]);
        }
    }
}

// ============ fused MLP (+optional final add in x-layout) ============
#define ASTM 200
#define HSTM 776
#define WSTM 200
#define W_TILE_M (32 * WSTM)
#define SM_A_OFF 0
#define SM_W_OFF (64 * ASTM)
#define SM_H_OFF (SM_W_OFF + 3 * W_TILE_M)
#define SMEM_MLP ((SM_H_OFF + 64 * HSTM) * 2)
__global__ __launch_bounds__(256, 1) void mlp_fused(
    const bf16* __restrict__ A, const bf16* __restrict__ W1,
    const float* __restrict__ b1, const bf16* __restrict__ W2,
    const float* __restrict__ b2, const float* __restrict__ res,
    float* __restrict__ outres, float* __restrict__ out_final,
    const float* __restrict__ xt) {
    pdl_sync();
    extern __shared__ char smraw[];
    bf16* sm = (bf16*)smraw;
    bf16* Asm = sm + SM_A_OFF;
    bf16* Ws  = sm + SM_W_OFF;
    bf16* hid = sm + SM_H_OFF;
    const int tid = threadIdx.x;
    const int lane = tid & 31;
    const int wid = tid >> 5;
    const int wm = wid >> 2, wn = wid & 3;
    const int row0 = blockIdx.x * 64;
    const int gq = lane >> 2, tq = lane & 3;

    const int lrow8 = (lane & 7) + 8 * ((lane >> 3) & 1);
    const int lcol8 = 8 * (lane >> 4);
    unsigned a_base = (unsigned)__cvta_generic_to_shared(Asm);
    unsigned w_base = (unsigned)__cvta_generic_to_shared(Ws);
    unsigned h_base = (unsigned)__cvta_generic_to_shared(hid);

#pragma unroll
    for (int i = 0; i < 6; i++) {
        int idx = tid + i * 256;
        int rr = idx / 24, ch = idx % 24;
        cp16(&Asm[rr * ASTM + ch * 8], &A[(size_t)(row0 + rr) * Cdim + ch * 8]);
    }
    asm volatile("cp.async.commit_group;");

    const int wrow = tid >> 3;
    const int wc0 = (tid & 7) * 8;

    auto load_w1 = [&](int stage, int k0, int n0) {
#pragma unroll
        for (int p = 0; p < 3; p++)
            cp16(&Ws[stage * W_TILE_M + wrow * WSTM + wc0 + p * 64],
                 &W1[(size_t)(k0 + wrow) * HIDN + n0 + wc0 + p * 64]);
        asm volatile("cp.async.commit_group;");
    };
    auto load_w2 = [&](int stage, int k0) {
#pragma unroll
        for (int p = 0; p < 3; p++)
            cp16(&Ws[stage * W_TILE_M + wrow * WSTM + wc0 + p * 64],
                 &W2[(size_t)(k0 + wrow) * Cdim + wc0 + p * 64]);
        asm volatile("cp.async.commit_group;");
    };

    unsigned af[2][2][4], bfr[2][6][2];
    auto frag_a = [&](int pb, unsigned abase, int stride, int kcol) {
#pragma unroll
        for (int i = 0; i < 2; i++) {
            unsigned addr = abase + (unsigned)(((wm * 32 + i * 16 + lrow8) * stride + kcol + lcol8) * 2);
            asm volatile("ldmatrix.sync.aligned.m8n8.x4.shared.b16 {%0,%1,%2,%3}, [%4];"
                         : "=r"(af[pb][i][0]), "=r"(af[pb][i][1]),
                           "=r"(af[pb][i][2]), "=r"(af[pb][i][3])
                         : "r"(addr));
        }
    };
    auto frag_b = [&](int pb, unsigned wbuf, int ks) {
#pragma unroll
        for (int jp = 0; jp < 3; jp++) {
            unsigned addr = wbuf + (unsigned)(((ks + lrow8) * WSTM + wn * 48 + jp * 16 + lcol8) * 2);
            asm volatile("ldmatrix.sync.aligned.m8n8.x4.trans.shared.b16 {%0,%1,%2,%3}, [%4];"
                         : "=r"(bfr[pb][jp * 2][0]), "=r"(bfr[pb][jp * 2][1]),
                           "=r"(bfr[pb][jp * 2 + 1][0]), "=r"(bfr[pb][jp * 2 + 1][1])
                         : "r"(addr));
        }
    };

#define MMA_STEP(pb)                                                                   \
    _Pragma("unroll")                                                                  \
    for (int i = 0; i < 2; i++)                                                        \
        _Pragma("unroll")                                                              \
        for (int j = 0; j < 6; j++) {                                                  \
            asm volatile(                                                              \
                "mma.sync.aligned.m16n8k16.row.col.f32.bf16.bf16.f32 "                 \
                "{%0,%1,%2,%3}, {%4,%5,%6,%7}, {%8,%9}, {%0,%1,%2,%3};"                \
                : "+f"(acc[i][j][0]), "+f"(acc[i][j][1]),                              \
                  "+f"(acc[i][j][2]), "+f"(acc[i][j][3])                               \
                : "r"(af[pb][i][0]), "r"(af[pb][i][1]),                                \
                  "r"(af[pb][i][2]), "r"(af[pb][i][3]),                                \
                  "r"(bfr[pb][j][0]), "r"(bfr[pb][j][1]));                             \
        }

    // phase 1: hid = gelu(A @ W1 + b1)
    for (int nc = 0; nc < 4; nc++) {
        int n0 = nc * 192;
        load_w1(0, 0, n0);
        load_w1(1, 32, n0);
        float acc[2][6][4] = {};
        for (int kt = 0; kt < 6; kt++) {
            if (kt + 1 < 6) asm volatile("cp.async.wait_group 1;");
            else            asm volatile("cp.async.wait_group 0;");
            __syncthreads();
            if (kt + 2 < 6) load_w1((kt + 2) % 3, (kt + 2) * 32, n0);
            unsigned wbuf = w_base + (kt % 3) * (W_TILE_M * 2);
#pragma unroll
            for (int ks = 0; ks < 32; ks += 16) {
                int pb = (ks >> 4) & 1;
                frag_a(pb, a_base, ASTM, kt * 32 + ks);
                frag_b(pb, wbuf, ks);
                MMA_STEP(pb)
            }
        }
#pragma unroll
        for (int i = 0; i < 2; i++) {
            int rl = wm * 32 + i * 16 + gq;
#pragma unroll
            for (int j = 0; j < 6; j++) {
                int c = wn * 48 + j * 8 + 2 * tq;
                int gc = n0 + c;
                float v0 = gelu_f(acc[i][j][0] + b1[gc]);
                float v1 = gelu_f(acc[i][j][1] + b1[gc + 1]);
                float v2 = gelu_f(acc[i][j][2] + b1[gc]);
                float v3 = gelu_f(acc[i][j][3] + b1[gc + 1]);
                hid[rl * HSTM + gc]           = __float2bfloat16(v0);
                hid[rl * HSTM + gc + 1]       = __float2bfloat16(v1);
                hid[(rl + 8) * HSTM + gc]     = __float2bfloat16(v2);
                hid[(rl + 8) * HSTM + gc + 1] = __float2bfloat16(v3);
            }
        }
    }

    // phase 2: out = hid @ W2 + b2 + res
    load_w2(0, 0);
    load_w2(1, 32);
    float acc[2][6][4] = {};
    for (int kt = 0; kt < 24; kt++) {
        if (kt + 1 < 24) asm volatile("cp.async.wait_group 1;");
        else             asm volatile("cp.async.wait_group 0;");
        __syncthreads();
        if (kt + 2 < 24) load_w2((kt + 2) % 3, (kt + 2) * 32);
        unsigned wbuf = w_base + (kt % 3) * (W_TILE_M * 2);
#pragma unroll
        for (int ks = 0; ks < 32; ks += 16) {
            int pb = (ks >> 4) & 1;
            frag_a(pb, h_base, HSTM, kt * 32 + ks);
            frag_b(pb, wbuf, ks);
            MMA_STEP(pb)
        }
    }
    pdl_trig();

    if (!out_final) {
#pragma unroll
        for (int i = 0; i < 2; i++) {
            int rl = wm * 32 + i * 16 + gq;
            size_t r = (size_t)(row0 + rl);
#pragma unroll
            for (int j = 0; j < 6; j++) {
                int c = wn * 48 + j * 8 + 2 * tq;
                outres[r * Cdim + c]           = acc[i][j][0] + b2[c]     + res[r * Cdim + c];
                outres[r * Cdim + c + 1]       = acc[i][j][1] + b2[c + 1] + res[r * Cdim + c + 1];
                outres[(r + 8) * Cdim + c]     = acc[i][j][2] + b2[c]     + res[(r + 8) * Cdim + c];
                outres[(r + 8) * Cdim + c + 1] = acc[i][j][3] + b2[c + 1] + res[(r + 8) * Cdim + c + 1];
            }
        }
    } else {
        float* stage = (float*)hid;
        __syncthreads();
#pragma unroll
        for (int i = 0; i < 2; i++) {
            int rl = wm * 32 + i * 16 + gq;
            size_t r = (size_t)(row0 + rl);
#pragma unroll
            for (int j = 0; j < 6; j++) {
                int c = wn * 48 + j * 8 + 2 * tq;
                stage[rl * 193 + c]           = acc[i][j][0] + b2[c]     + res[r * Cdim + c];
                stage[rl * 193 + c + 1]       = acc[i][j][1] + b2[c + 1] + res[r * Cdim + c + 1];
                stage[(rl + 8) * 193 + c]     = acc[i][j][2] + b2[c]     + res[(r + 8) * Cdim + c];
                stage[(rl + 8) * 193 + c + 1] = acc[i][j][3] + b2[c + 1] + res[(r + 8) * Cdim + c + 1];
            }
        }
        __syncthreads();
        int sfr = row0 >> 10;
        int hw0l = row0 & 1023;
#pragma unroll
        for (int i = 0; i < 48; i++) {
            int idx = tid + i * 256;
            int c = idx >> 6, hwl = idx & 63;
            size_t xi = ((size_t)c * 8 + sfr) * 1024 + hw0l + hwl;
            out_final[xi] = xt[xi] + stage[hwl * 193 + c];
        }
    }
#undef MMA_STEP
}

// ---------------- time attention ----------------
__global__ void time_attn_kernel() {
    pdl_sync();
    int n = blockIdx.x;
    int h = threadIdx.x >> 5, lane = threadIdx.x & 31;
    const bf16* base = g_qkvb + (size_t)n * 8 * (3 * Cdim);
    float kreg[8], vreg[8];
#pragma unroll
    for (int j = 0; j < 8; j++) {
        kreg[j] = __bfloat162float(base[j * 576 + Cdim + h * 32 + lane]);
        vreg[j] = __bfloat162float(base[j * 576 + 2 * Cdim + h * 32 + lane]);
    }
#pragma unroll
    for (int s = 0; s < 8; s++) {
        float qv = __bfloat162float(base[s * 576 + h * 32 + lane]);
        float sc[8];
#pragma unroll
        for (int j = 0; j < 8; j++) sc[j] = warp_sum(qv * kreg[j]) * SCALE;
        float mx = sc[0];
#pragma unroll
        for (int j = 1; j < 8; j++) mx = fmaxf(mx, sc[j]);
        float sum = 0.f, o = 0.f;
#pragma unroll
        for (int j = 0; j < 8; j++) {
            float p = __expf(sc[j] - mx);
            sum += p;
            o += p * vreg[j];
        }
        g_ob[(size_t)(n * 8 + s) * Cdim + h * 32 + lane] = __float2bfloat16(o / sum);
    }
    pdl_trig();
}

// ---------------- NAT attention ----------------
__global__ void nat_attn_kernel(const float* __restrict__ rpb) {
    pdl_sync();
    int f = blockIdx.x >> 5;
    int hh = blockIdx.x & 31;
    int wno = threadIdx.x >> 5, lane = threadIdx.x & 31;
    int h = wno % NHEAD, half = wno / NHEAD;
    __shared__ float sc[12][52];
    int sh0 = min(max(hh - 3, 0), 25);
    int ww0 = half * 16;
    for (int ww = ww0; ww < ww0 + 16; ww++) {
        size_t m = (size_t)f * 1024 + hh * 32 + ww;
        float qv = __bfloat162float(g_qkvb[m * 576 + h * 32 + lane]) * SCALE;
        int sw0 = min(max(ww - 3, 0), 25);
#pragma unroll
        for (int a = 0; a < 7; a++) {
            int ia = sh0 + a;
            int rh = ia - hh + 6;
            const bf16* krow = g_qkvb + ((size_t)f * 1024 + ia * 32 + sw0) * 576 + Cdim + h * 32 + lane;
#pragma unroll
            for (int b = 0; b < 7; b++) {
                float d = warp_sum(qv * __bfloat162float(krow[b * 576]));
                if (lane == 0) {
                    int rw = sw0 + b - ww + 6;
                    sc[wno][a * 7 + b] = d + rpb[h * 169 + rh * 13 + rw];
                }
            }
        }
        __syncwarp();
        float mx = -1e30f;
#pragma unroll
        for (int n2 = 0; n2 < 49; n2++) mx = fmaxf(mx, sc[wno][n2]);
        float sum = 0.f, o = 0.f;
#pragma unroll
        for (int a = 0; a < 7; a++) {
            int ia = sh0 + a;
            const bf16* vrow = g_qkvb + ((size_t)f * 1024 + ia * 32 + sw0) * 576 + 2 * Cdim + h * 32 + lane;
#pragma unroll
            for (int b = 0; b < 7; b++) {
                float p = __expf(sc[wno][a * 7 + b] - mx);
                sum += p;
                o += p * __bfloat162float(vrow[b * 576]);
            }
        }
        g_ob[m * Cdim + h * 32 + lane] = __float2bfloat16(o / sum);
        __syncwarp();
    }
    pdl_trig();
}

// ---------------- PDL launch helper ----------------
template <typename F, typename... Args>
static void pdl_launch(dim3 grid, dim3 block, size_t smem, F* kern, Args... args) {
    cudaLaunchConfig_t cfg = {};
    cfg.gridDim = grid;
    cfg.blockDim = block;
    cfg.dynamicSmemBytes = smem;
    cfg.stream = 0;
    cudaLaunchAttribute at[1];
    at[0].id = cudaLaunchAttributeProgrammaticStreamSerialization;
    at[0].val.programmaticStreamSerializationAllowed = 1;
    cfg.attrs = at;
    cfg.numAttrs = 1;
    cudaLaunchKernelEx(&cfg, kern, args...);
}

extern "C" void kernel_launch(void* const* d_in, const int* in_sizes, int n_in,
                              void* d_out, int out_size) {
    const float* x        = (const float*)d_in[0];
    const float* pos_emb  = (const float*)d_in[1];
    const float* t_ln1_g  = (const float*)d_in[2];
    const float* t_ln1_b  = (const float*)d_in[3];
    const float* t_qkv_w  = (const float*)d_in[4];
    const float* t_out_w  = (const float*)d_in[5];
    const float* t_out_b  = (const float*)d_in[6];
    const float* t_ln2_g  = (const float*)d_in[7];
    const float* t_ln2_b  = (const float*)d_in[8];
    const float* t_fc1_w  = (const float*)d_in[9];
    const float* t_fc1_b  = (const float*)d_in[10];
    const float* t_fc2_w  = (const float*)d_in[11];
    const float* t_fc2_b  = (const float*)d_in[12];
    const float* t_lnf_g  = (const float*)d_in[13];
    const float* t_lnf_b  = (const float*)d_in[14];
    const float* s_ln1_g  = (const float*)d_in[15];
    const float* s_ln1_b  = (const float*)d_in[16];
    const float* s_qkv_w  = (const float*)d_in[17];
    const float* s_qkv_b  = (const float*)d_in[18];
    const float* s_rpb    = (const float*)d_in[19];
    const float* s_proj_w = (const float*)d_in[20];
    const float* s_proj_b = (const float*)d_in[21];
    const float* s_ln2_g  = (const float*)d_in[22];
    const float* s_ln2_b  = (const float*)d_in[23];
    const float* s_fc1_w  = (const float*)d_in[24];
    const float* s_fc1_b  = (const float*)d_in[25];
    const float* s_fc2_w  = (const float*)d_in[26];
    const float* s_fc2_b  = (const float*)d_in[27];
    float* out = (float*)d_out;

    float *p_t, *p_s, *p_xt;
    bf16 *p_yb, *p_ob, *p_wb, *p_qkvb;
    cudaGetSymbolAddress((void**)&p_t, g_t);
    cudaGetSymbolAddress((void**)&p_s, g_s);
    cudaGetSymbolAddress((void**)&p_xt, g_xt);
    cudaGetSymbolAddress((void**)&p_yb, g_yb);
    cudaGetSymbolAddress((void**)&p_ob, g_ob);
    cudaGetSymbolAddress((void**)&p_wb, g_wb);
    cudaGetSymbolAddress((void**)&p_qkvb, g_qkvb);

    const int SMEM_LN = 3 * A_TILE_L * 2 + 3 * B_TILE_L * 2;
    cudaFuncSetAttribute(gemm_ln, cudaFuncAttributeMaxDynamicSharedMemorySize, SMEM_LN);
    cudaFuncSetAttribute(mlp_fused, cudaFuncAttributeMaxDynamicSharedMemorySize, SMEM_MLP);

    convert_build_kernel<<<256 + 3456, 256>>>(x, pos_emb, t_ln1_g, t_ln1_b,
                                              t_qkv_w, t_out_w, t_fc1_w, t_fc2_w,
                                              s_qkv_w, s_proj_w, s_fc1_w, s_fc2_w);

    // ======== time transformer ========
    pdl_launch(dim3(9, 64), dim3(256), 0, gemm_bf16,
               (const bf16*)p_yb, (const bf16*)(p_wb + OFF_TQKV), (const float*)nullptr,
               p_qkvb, NTOK, 576, Cdim);
    pdl_launch(dim3(1024), dim3(192), 0, time_attn_kernel);
    pdl_launch(dim3(128), dim3(256), (size_t)SMEM_LN, gemm_ln,
               (const bf16*)p_ob, (const bf16*)(p_wb + OFF_TOUT), t_out_b, (const float*)p_t,
               p_t, p_yb, t_ln2_g, t_ln2_b, Cdim);
    pdl_launch(dim3(128), dim3(256), (size_t)SMEM_MLP, mlp_fused,
               (const bf16*)p_yb, (const bf16*)(p_wb + OFF_TFC1), t_fc1_b,
               (const bf16*)(p_wb + OFF_TFC2), t_fc2_b, (const float*)p_t,
               p_t, (float*)nullptr, (const float*)nullptr);
    pdl_launch(dim3(8, 32), dim3(32, 8), 0, lnf_add_kernel,
               x, t_lnf_g, t_lnf_b, s_ln1_g, s_ln1_b);

    // ======== space transformer (NAT) ========
    pdl_launch(dim3(9, 64), dim3(256), 0, gemm_bf16,
               (const bf16*)p_yb, (const bf16*)(p_wb + OFF_SQKV), s_qkv_b,
               p_qkvb, NTOK, 576, Cdim);
    pdl_launch(dim3(256), dim3(384), 0, nat_attn_kernel, s_rpb);
    pdl_launch(dim3(128), dim3(256), (size_t)SMEM_LN, gemm_ln,
               (const bf16*)p_ob, (const bf16*)(p_wb + OFF_SPROJ), s_proj_b, (const float*)p_s,
               p_s, p_yb, s_ln2_g, s_ln2_b, Cdim);
    pdl_launch(dim3(128), dim3(256), (size_t)SMEM_MLP, mlp_fused,
               (const bf16*)p_yb, (const bf16*)(p_wb + OFF_SFC1), s_fc1_b,
               (const bf16*)(p_wb + OFF_SFC2), s_fc2_b, (const float*)p_s,
               (float*)nullptr, out, (const float*)p_xt);
}

// round 15
// speedup vs baseline: 1.0417x; 1.0417x over previous
#include <cuda_runtime.h>
#include <cuda_bf16.h>
#include <stdint.h>
#include <math.h>

#define Cdim 192
#define Dn 8
#define Hn 32
#define Wn 32
#define NHEAD 6
#define HDIM 32
#define HIDN 768
#define NTOK 8192
#define SCALE 0.17677669529663687f

typedef __nv_bfloat16 bf16;

// ---------------- scratch ----------------
__device__ float g_t[NTOK * Cdim];
__device__ float g_xt[Cdim * Dn * Hn * Wn];
__device__ float g_s[NTOK * Cdim];
__device__ bf16  g_qkvb[NTOK * 3 * Cdim];
__device__ bf16  g_yb[NTOK * Cdim];
__device__ bf16  g_ob[NTOK * Cdim];
__device__ bf16  g_wb[884736];

#define OFF_TQKV 0
#define OFF_TOUT 110592
#define OFF_TFC1 147456
#define OFF_TFC2 294912
#define OFF_SQKV 442368
#define OFF_SPROJ 552960
#define OFF_SFC1 589824
#define OFF_SFC2 737280

__device__ __forceinline__ float warp_sum(float v) {
#pragma unroll
    for (int o = 16; o > 0; o >>= 1) v += __shfl_xor_sync(0xffffffffu, v, o);
    return v;
}

__device__ __forceinline__ void cp16(void* dst, const void* src) {
    unsigned d = (unsigned)__cvta_generic_to_shared(dst);
    asm volatile("cp.async.cg.shared.global [%0], [%1], 16;" :: "r"(d), "l"(src));
}

__device__ __forceinline__ float gelu_f(float v) {
    return 0.5f * v * (1.0f + erff(v * 0.7071067811865476f));
}

// ---------------- kernel 1: convert weights + build t + LN1 (merged) -----------
__global__ void convert_build_kernel(
    const float* __restrict__ x, const float* __restrict__ pe,
    const float* __restrict__ g, const float* __restrict__ b,
    const float* __restrict__ a0, const float* __restrict__ a1,
    const float* __restrict__ a2, const float* __restrict__ a3,
    const float* __restrict__ a4, const float* __restrict__ a5,
    const float* __restrict__ a6, const float* __restrict__ a7) {
    int blk = blockIdx.x;
    int tid = threadIdx.x;
    if (blk >= 256) {
        int i = (blk - 256) * 256 + tid;
        const float* src; int off;
        if      (i < 110592) { src = a0; off = 0; }
        else if (i < 147456) { src = a1; off = 110592; }
        else if (i < 294912) { src = a2; off = 147456; }
        else if (i < 442368) { src = a3; off = 294912; }
        else if (i < 552960) { src = a4; off = 442368; }
        else if (i < 589824) { src = a5; off = 552960; }
        else if (i < 737280) { src = a6; off = 589824; }
        else                 { src = a7; off = 737280; }
        g_wb[i] = __float2bfloat16(src[i - off]);
        return;
    }
    __shared__ float xsm[Cdim][33];
    int s = blk >> 5;
    int hw0 = (blk & 31) * 32;
    int tx = tid & 31, ty = tid >> 5;
    int warp = ty, lane = tx;

#pragma unroll
    for (int i = 0; i < 24; i++) {
        int c = ty + 8 * i;
        xsm[c][tx] = x[((size_t)c * 8 + s) * 1024 + hw0 + tx] + pe[s * Cdim + c];
    }
    __syncthreads();

#pragma unroll
    for (int i = 0; i < 4; i++) {
        int hwl = warp + 8 * i;
        size_t r = (size_t)(hw0 + hwl) * 8 + s;
        float v[6];
        float sum = 0.f;
#pragma unroll
        for (int j = 0; j < 6; j++) { v[j] = xsm[lane + 32 * j][hwl]; sum += v[j]; }
        sum = warp_sum(sum);
        float m = sum * (1.0f / Cdim);
        float var = 0.f;
#pragma unroll
        for (int j = 0; j < 6; j++) { float d = v[j] - m; var += d * d; }
        var = warp_sum(var) * (1.0f / Cdim);
        float rstd = rsqrtf(var + 1e-5f);
#pragma unroll
        for (int j = 0; j < 6; j++) {
            int c = lane + 32 * j;
            g_t[r * Cdim + c] = v[j];
            g_yb[r * Cdim + c] = __float2bfloat16((v[j] - m) * rstd * g[c] + b[c]);
        }
    }
}

// ---------------- fused: y = LNf(t); xt = x + y^T; s-stream + s_ln1 ------------
__global__ void lnf_add_kernel(const float* __restrict__ x,
                               const float* __restrict__ g, const float* __restrict__ b,
                               const float* __restrict__ g2, const float* __restrict__ b2) {
    __shared__ float vsm[Cdim][33];
    int s = blockIdx.x;
    int hw0 = blockIdx.y * 32;
    int tx = threadIdx.x, ty = threadIdx.y;
    int tid = ty * 32 + tx;
    int warp = tid >> 5, lane = tid & 31;

#pragma unroll
    for (int i = 0; i < 4; i++) {
        int hwl = warp + 8 * i;
        size_t r = (size_t)(hw0 + hwl) * 8 + s;
        float v[6];
        float sum = 0.f;
#pragma unroll
        for (int j = 0; j < 6; j++) { v[j] = g_t[r * Cdim + lane + 32 * j]; sum += v[j]; }
        sum = warp_sum(sum);
        float m = sum * (1.0f / Cdim);
        float var = 0.f;
#pragma unroll
        for (int j = 0; j < 6; j++) { float d = v[j] - m; var += d * d; }
        var = warp_sum(var) * (1.0f / Cdim);
        float rstd = rsqrtf(var + 1e-5f);
#pragma unroll
        for (int j = 0; j < 6; j++) {
            int c = lane + 32 * j;
            vsm[c][hwl] = (v[j] - m) * rstd * g[c] + b[c];
        }
    }
    __syncthreads();

#pragma unroll
    for (int i = 0; i < 24; i++) {
        int c = ty + 8 * i;
        size_t xi = ((size_t)c * 8 + s) * 1024 + hw0 + tx;
        float val = x[xi] + vsm[c][tx];
        g_xt[xi] = val;
        vsm[c][tx] = val;
    }
    __syncthreads();

#pragma unroll
    for (int i = 0; i < 4; i++) {
        int hwl = warp + 8 * i;
        size_t r = (size_t)s * 1024 + hw0 + hwl;
        float v[6];
        float sum = 0.f;
#pragma unroll
        for (int j = 0; j < 6; j++) { v[j] = vsm[lane + 32 * j][hwl]; sum += v[j]; }
        sum = warp_sum(sum);
        float m = sum * (1.0f / Cdim);
        float var = 0.f;
#pragma unroll
        for (int j = 0; j < 6; j++) { float d = v[j] - m; var += d * d; }
        var = warp_sum(var) * (1.0f / Cdim);
        float rstd = rsqrtf(var + 1e-5f);
#pragma unroll
        for (int j = 0; j < 6; j++) {
            int c = lane + 32 * j;
            g_s[r * Cdim + c] = v[j];
            g_yb[r * Cdim + c] = __float2bfloat16((v[j] - m) * rstd * g2[c] + b2[c]);
        }
    }
}

#define AST 40
#define BST 72

// ============ wide GEMM: BM=128, BN=64, BK=32, 3-stage ring (qkv) ============
#define A_TILE (128 * AST)
#define B_TILE (32 * BST)
__global__ __launch_bounds__(256) void gemm_bf16(
    const bf16* __restrict__ A, const bf16* __restrict__ B,
    const float* __restrict__ bias, bf16* __restrict__ outb,
    int M, int N, int K) {
    __shared__ bf16 As[3][A_TILE];
    __shared__ bf16 Bs[3][B_TILE];
    const int tid = threadIdx.x;
    const int lane = tid & 31;
    const int wid = tid >> 5;
    const int wm = wid >> 1, wn = wid & 1;
    const int row0 = blockIdx.y * 128, col0 = blockIdx.x * 64;
    const int gq = lane >> 2, tq = lane & 3;

    const int lrow8 = (lane & 7) + 8 * ((lane >> 3) & 1);
    const int lcol8 = 8 * (lane >> 4);
    unsigned as_base = (unsigned)__cvta_generic_to_shared(&As[0][0]);
    unsigned bs_base = (unsigned)__cvta_generic_to_shared(&Bs[0][0]);

    float acc[2][4][4] = {};

    const int a_m = (tid >> 2), a_q = (tid & 3);
    const int b_k = (tid >> 3), b_q = (tid & 7);

    auto load_tile = [&](int buf, int k0) {
#pragma unroll
        for (int j = 0; j < 2; j++) {
            int m = a_m + j * 64;
            cp16(&As[buf][m * AST + a_q * 8], &A[(size_t)(row0 + m) * K + k0 + a_q * 8]);
        }
        cp16(&Bs[buf][b_k * BST + b_q * 8], &B[(size_t)(k0 + b_k) * N + col0 + b_q * 8]);
        asm volatile("cp.async.commit_group;");
    };

    unsigned af[2][2][4], bfr[2][4][2];
    auto load_frag = [&](int pb, unsigned abuf, unsigned bbuf, int ks) {
#pragma unroll
        for (int i = 0; i < 2; i++) {
            unsigned addr = abuf + (unsigned)(((wm * 32 + i * 16 + lrow8) * AST + ks + lcol8) * 2);
            asm volatile("ldmatrix.sync.aligned.m8n8.x4.shared.b16 {%0,%1,%2,%3}, [%4];"
                         : "=r"(af[pb][i][0]), "=r"(af[pb][i][1]),
                           "=r"(af[pb][i][2]), "=r"(af[pb][i][3])
                         : "r"(addr));
        }
#pragma unroll
        for (int jp = 0; jp < 2; jp++) {
            unsigned addr = bbuf + (unsigned)(((ks + lrow8) * BST + wn * 32 + jp * 16 + lcol8) * 2);
            asm volatile("ldmatrix.sync.aligned.m8n8.x4.trans.shared.b16 {%0,%1,%2,%3}, [%4];"
                         : "=r"(bfr[pb][jp * 2][0]), "=r"(bfr[pb][jp * 2][1]),
                           "=r"(bfr[pb][jp * 2 + 1][0]), "=r"(bfr[pb][jp * 2 + 1][1])
                         : "r"(addr));
        }
    };

    const int nk = K / 32;
    load_tile(0, 0);
    if (nk > 1) load_tile(1, 32);

    for (int it = 0; it < nk; it++) {
        if (it + 1 < nk) asm volatile("cp.async.wait_group 1;");
        else             asm volatile("cp.async.wait_group 0;");
        __syncthreads();
        if (it + 2 < nk) load_tile((it + 2) % 3, (it + 2) * 32);

        int buf = it % 3;
        unsigned abuf = as_base + buf * (A_TILE * 2);
        unsigned bbuf = bs_base + buf * (B_TILE * 2);
        load_frag(0, abuf, bbuf, 0);
#pragma unroll
        for (int ks = 0; ks < 2; ks++) {
            int pb = ks & 1;
            if (ks < 1) load_frag(pb ^ 1, abuf, bbuf, 16);
#pragma unroll
            for (int i = 0; i < 2; i++)
#pragma unroll
                for (int j = 0; j < 4; j++) {
                    asm volatile(
                        "mma.sync.aligned.m16n8k16.row.col.f32.bf16.bf16.f32 "
                        "{%0,%1,%2,%3}, {%4,%5,%6,%7}, {%8,%9}, {%0,%1,%2,%3};"
                        : "+f"(acc[i][j][0]), "+f"(acc[i][j][1]),
                          "+f"(acc[i][j][2]), "+f"(acc[i][j][3])
                        : "r"(af[pb][i][0]), "r"(af[pb][i][1]),
                          "r"(af[pb][i][2]), "r"(af[pb][i][3]),
                          "r"(bfr[pb][j][0]), "r"(bfr[pb][j][1]));
                }
        }
    }

#pragma unroll
    for (int i = 0; i < 2; i++) {
        int r = row0 + wm * 32 + i * 16 + gq;
#pragma unroll
        for (int j = 0; j < 4; j++) {
            int c = col0 + wn * 32 + j * 8 + 2 * tq;
            float v0 = acc[i][j][0], v1 = acc[i][j][1];
            float v2 = acc[i][j][2], v3 = acc[i][j][3];
            if (bias) {
                float b0 = bias[c], b1 = bias[c + 1];
                v0 += b0; v1 += b1; v2 += b0; v3 += b1;
            }
            outb[(size_t)r * N + c]           = __float2bfloat16(v0);
            outb[(size_t)r * N + c + 1]       = __float2bfloat16(v1);
            outb[(size_t)(r + 8) * N + c]     = __float2bfloat16(v2);
            outb[(size_t)(r + 8) * N + c + 1] = __float2bfloat16(v3);
        }
    }
}

// ============ fused GEMM+LN: BM=64, BN=192, 512 threads (16 warps 4x4) =========
#define ASTL 40
#define BSTL 200
#define A_TILE_L (64 * ASTL)
#define B_TILE_L (32 * BSTL)
__global__ __launch_bounds__(512) void gemm_ln(
    const bf16* __restrict__ A, const bf16* __restrict__ B,
    const float* __restrict__ bias, const float* __restrict__ res,
    float* __restrict__ outres, bf16* __restrict__ outln,
    const float* __restrict__ lng, const float* __restrict__ lnb,
    int K) {
    extern __shared__ char smraw[];
    bf16* As = (bf16*)smraw;
    bf16* Bs = (bf16*)smraw + 3 * A_TILE_L;
    float* epi = (float*)smraw;
    const int tid = threadIdx.x;
    const int lane = tid & 31;
    const int wid = tid >> 5;
    const int wm = wid >> 2, wn = wid & 3;   // 4x4 warps, warp tile 16x48
    const int row0 = blockIdx.x * 64;
    const int gq = lane >> 2, tq = lane & 3;

    const int lrow8 = (lane & 7) + 8 * ((lane >> 3) & 1);
    const int lcol8 = 8 * (lane >> 4);
    unsigned as_base = (unsigned)__cvta_generic_to_shared(As);
    unsigned bs_base = (unsigned)__cvta_generic_to_shared(Bs);

    float acc[6][4] = {};

    auto load_tile = [&](int buf, int k0) {
#pragma unroll
        for (int t = 0; t < 2; t++) {
            int idx = tid + t * 512;
            if (idx < 256) {
                int am = idx >> 2, aq = idx & 3;
                cp16(&As[buf * A_TILE_L + am * ASTL + aq * 8],
                     &A[(size_t)(row0 + am) * K + k0 + aq * 8]);
            } else {
                int q = idx - 256;
                int br = q / 24, bc = q % 24;
                cp16(&Bs[buf * B_TILE_L + br * BSTL + bc * 8],
                     &B[(size_t)(k0 + br) * Cdim + bc * 8]);
            }
        }
        asm volatile("cp.async.commit_group;");
    };

    unsigned af[2][4], bfr[2][6][2];
    auto load_frag = [&](int pb, unsigned abuf, unsigned bbuf, int ks) {
        {
            unsigned addr = abuf + (unsigned)(((wm * 16 + lrow8) * ASTL + ks + lcol8) * 2);
            asm volatile("ldmatrix.sync.aligned.m8n8.x4.shared.b16 {%0,%1,%2,%3}, [%4];"
                         : "=r"(af[pb][0]), "=r"(af[pb][1]),
                           "=r"(af[pb][2]), "=r"(af[pb][3])
                         : "r"(addr));
        }
#pragma unroll
        for (int jp = 0; jp < 3; jp++) {
            unsigned addr = bbuf + (unsigned)(((ks + lrow8) * BSTL + wn * 48 + jp * 16 + lcol8) * 2);
            asm volatile("ldmatrix.sync.aligned.m8n8.x4.trans.shared.b16 {%0,%1,%2,%3}, [%4];"
                         : "=r"(bfr[pb][jp * 2][0]), "=r"(bfr[pb][jp * 2][1]),
                           "=r"(bfr[pb][jp * 2 + 1][0]), "=r"(bfr[pb][jp * 2 + 1][1])
                         : "r"(addr));
        }
    };

    const int nk = K / 32;
    load_tile(0, 0);
    if (nk > 1) load_tile(1, 32);

    for (int it = 0; it < nk; it++) {
        if (it + 1 < nk) asm volatile("cp.async.wait_group 1;");
        else             asm volatile("cp.async.wait_group 0;");
        __syncthreads();
        if (it + 2 < nk) load_tile((it + 2) % 3, (it + 2) * 32);

        int buf = it % 3;
        unsigned abuf = as_base + buf * (A_TILE_L * 2);
        unsigned bbuf = bs_base + buf * (B_TILE_L * 2);
        load_frag(0, abuf, bbuf, 0);
#pragma unroll
        for (int ks = 0; ks < 2; ks++) {
            int pb = ks & 1;
            if (ks < 1) load_frag(pb ^ 1, abuf, bbuf, 16);
#pragma unroll
            for (int j = 0; j < 6; j++) {
                asm volatile(
                    "mma.sync.aligned.m16n8k16.row.col.f32.bf16.bf16.f32 "
                    "{%0,%1,%2,%3}, {%4,%5,%6,%7}, {%8,%9}, {%0,%1,%2,%3};"
                    : "+f"(acc[j][0]), "+f"(acc[j][1]),
                      "+f"(acc[j][2]), "+f"(acc[j][3])
                    : "r"(af[pb][0]), "r"(af[pb][1]),
                      "r"(af[pb][2]), "r"(af[pb][3]),
                      "r"(bfr[pb][j][0]), "r"(bfr[pb][j][1]));
            }
        }
    }
    __syncthreads();

    // epilogue phase A: bias + residual -> epi smem
    {
        int rl = wm * 16 + gq;
        size_t r = (size_t)(row0 + rl);
#pragma unroll
        for (int j = 0; j < 6; j++) {
            int c = wn * 48 + j * 8 + 2 * tq;
            epi[rl * 193 + c]           = acc[j][0] + bias[c]     + res[r * Cdim + c];
            epi[rl * 193 + c + 1]       = acc[j][1] + bias[c + 1] + res[r * Cdim + c + 1];
            epi[(rl + 8) * 193 + c]     = acc[j][2] + bias[c]     + res[(r + 8) * Cdim + c];
            epi[(rl + 8) * 193 + c + 1] = acc[j][3] + bias[c + 1] + res[(r + 8) * Cdim + c + 1];
        }
    }
    __syncthreads();

    // epilogue phase B: per-row LN (16 warps, 4 rows each)
#pragma unroll
    for (int rr = 0; rr < 4; rr++) {
        int rl = wid * 4 + rr;
        size_t r = (size_t)(row0 + rl);
        float v[6];
        float sum = 0.f;
#pragma unroll
        for (int j = 0; j < 6; j++) { v[j] = epi[rl * 193 + lane + 32 * j]; sum += v[j]; }
        sum = warp_sum(sum);
        float m = sum * (1.0f / Cdim);
        float var = 0.f;
#pragma unroll
        for (int j = 0; j < 6; j++) { float d = v[j] - m; var += d * d; }
        var = warp_sum(var) * (1.0f / Cdim);
        float rstd = rsqrtf(var + 1e-5f);
#pragma unroll
        for (int j = 0; j < 6; j++) {
            int c = lane + 32 * j;
            outres[r * Cdim + c] = v[j];
            outln[r * Cdim + c] = __float2bfloat16((v[j] - m) * rstd * lng[c] + lnb[c]);
        }
    }
}

// ============ fused MLP, 512 threads (16 warps 4x4, warp tile 16x48) ============
#define ASTM 200
#define HSTM 776
#define WSTM 200
#define W_TILE_M (32 * WSTM)
#define SM_A_OFF 0
#define SM_W_OFF (64 * ASTM)
#define SM_H_OFF (SM_W_OFF + 3 * W_TILE_M)
#define SMEM_MLP ((SM_H_OFF + 64 * HSTM) * 2)
__global__ __launch_bounds__(512, 1) void mlp_fused(
    const bf16* __restrict__ A, const bf16* __restrict__ W1,
    const float* __restrict__ b1, const bf16* __restrict__ W2,
    const float* __restrict__ b2, const float* __restrict__ res,
    float* __restrict__ outres, float* __restrict__ out_final,
    const float* __restrict__ xt) {
    extern __shared__ char smraw[];
    bf16* sm = (bf16*)smraw;
    bf16* Asm = sm + SM_A_OFF;
    bf16* Ws  = sm + SM_W_OFF;
    bf16* hid = sm + SM_H_OFF;
    const int tid = threadIdx.x;
    const int lane = tid & 31;
    const int wid = tid >> 5;
    const int wm = wid >> 2, wn = wid & 3;   // 4x4, warp tile 16x48
    const int row0 = blockIdx.x * 64;
    const int gq = lane >> 2, tq = lane & 3;

    const int lrow8 = (lane & 7) + 8 * ((lane >> 3) & 1);
    const int lcol8 = 8 * (lane >> 4);
    unsigned a_base = (unsigned)__cvta_generic_to_shared(Asm);
    unsigned w_base = (unsigned)__cvta_generic_to_shared(Ws);
    unsigned h_base = (unsigned)__cvta_generic_to_shared(hid);

    // load A (64x192) once: 1536 chunks over 512 threads
#pragma unroll
    for (int i = 0; i < 3; i++) {
        int idx = tid + i * 512;
        int rr = idx / 24, ch = idx % 24;
        cp16(&Asm[rr * ASTM + ch * 8], &A[(size_t)(row0 + rr) * Cdim + ch * 8]);
    }
    asm volatile("cp.async.commit_group;");

    auto load_w1 = [&](int stage, int k0, int n0) {
#pragma unroll
        for (int t = 0; t < 2; t++) {
            int idx = tid + t * 512;
            if (idx < 768) {
                int row = idx / 24, cc = (idx % 24) * 8;
                cp16(&Ws[stage * W_TILE_M + row * WSTM + cc],
                     &W1[(size_t)(k0 + row) * HIDN + n0 + cc]);
            }
        }
        asm volatile("cp.async.commit_group;");
    };
    auto load_w2 = [&](int stage, int k0) {
#pragma unroll
        for (int t = 0; t < 2; t++) {
            int idx = tid + t * 512;
            if (idx < 768) {
                int row = idx / 24, cc = (idx % 24) * 8;
                cp16(&Ws[stage * W_TILE_M + row * WSTM + cc],
                     &W2[(size_t)(k0 + row) * Cdim + cc]);
            }
        }
        asm volatile("cp.async.commit_group;");
    };

    unsigned af[2][4], bfr[2][6][2];
    auto frag_a = [&](int pb, unsigned abase, int stride, int kcol) {
        unsigned addr = abase + (unsigned)(((wm * 16 + lrow8) * stride + kcol + lcol8) * 2);
        asm volatile("ldmatrix.sync.aligned.m8n8.x4.shared.b16 {%0,%1,%2,%3}, [%4];"
                     : "=r"(af[pb][0]), "=r"(af[pb][1]),
                       "=r"(af[pb][2]), "=r"(af[pb][3])
                     : "r"(addr));
    };
    auto frag_b = [&](int pb, unsigned wbuf, int ks) {
#pragma unroll
        for (int jp = 0; jp < 3; jp++) {
            unsigned addr = wbuf + (unsigned)(((ks + lrow8) * WSTM + wn * 48 + jp * 16 + lcol8) * 2);
            asm volatile("ldmatrix.sync.aligned.m8n8.x4.trans.shared.b16 {%0,%1,%2,%3}, [%4];"
                         : "=r"(bfr[pb][jp * 2][0]), "=r"(bfr[pb][jp * 2][1]),
                           "=r"(bfr[pb][jp * 2 + 1][0]), "=r"(bfr[pb][jp * 2 + 1][1])
                         : "r"(addr));
        }
    };

#define MMA_STEP(pb)                                                                   \
    _Pragma("unroll")                                                                  \
    for (int j = 0; j < 6; j++) {                                                      \
        asm volatile(                                                                  \
            "mma.sync.aligned.m16n8k16.row.col.f32.bf16.bf16.f32 "                     \
            "{%0,%1,%2,%3}, {%4,%5,%6,%7}, {%8,%9}, {%0,%1,%2,%3};"                    \
            : "+f"(acc[j][0]), "+f"(acc[j][1]),                                        \
              "+f"(acc[j][2]), "+f"(acc[j][3])                                         \
            : "r"(af[pb][0]), "r"(af[pb][1]),                                          \
              "r"(af[pb][2]), "r"(af[pb][3]),                                          \
              "r"(bfr[pb][j][0]), "r"(bfr[pb][j][1]));                                 \
    }

    // phase 1: hid = gelu(A @ W1 + b1)
    for (int nc = 0; nc < 4; nc++) {
        int n0 = nc * 192;
        load_w1(0, 0, n0);
        load_w1(1, 32, n0);
        float acc[6][4] = {};
        for (int kt = 0; kt < 6; kt++) {
            if (kt + 1 < 6) asm volatile("cp.async.wait_group 1;");
            else            asm volatile("cp.async.wait_group 0;");
            __syncthreads();
            if (kt + 2 < 6) load_w1((kt + 2) % 3, (kt + 2) * 32, n0);
            unsigned wbuf = w_base + (kt % 3) * (W_TILE_M * 2);
#pragma unroll
            for (int ks = 0; ks < 32; ks += 16) {
                int pb = (ks >> 4) & 1;
                frag_a(pb, a_base, ASTM, kt * 32 + ks);
                frag_b(pb, wbuf, ks);
                MMA_STEP(pb)
            }
        }
        {
            int rl = wm * 16 + gq;
#pragma unroll
            for (int j = 0; j < 6; j++) {
                int c = wn * 48 + j * 8 + 2 * tq;
                int gc = n0 + c;
                hid[rl * HSTM + gc]           = __float2bfloat16(gelu_f(acc[j][0] + b1[gc]));
                hid[rl * HSTM + gc + 1]       = __float2bfloat16(gelu_f(acc[j][1] + b1[gc + 1]));
                hid[(rl + 8) * HSTM + gc]     = __float2bfloat16(gelu_f(acc[j][2] + b1[gc]));
                hid[(rl + 8) * HSTM + gc + 1] = __float2bfloat16(gelu_f(acc[j][3] + b1[gc + 1]));
            }
        }
    }

    // phase 2: out = hid @ W2 + b2 + res
    load_w2(0, 0);
    load_w2(1, 32);
    float acc[6][4] = {};
    for (int kt = 0; kt < 24; kt++) {
        if (kt + 1 < 24) asm volatile("cp.async.wait_group 1;");
        else             asm volatile("cp.async.wait_group 0;");
        __syncthreads();
        if (kt + 2 < 24) load_w2((kt + 2) % 3, (kt + 2) * 32);
        unsigned wbuf = w_base + (kt % 3) * (W_TILE_M * 2);
#pragma unroll
        for (int ks = 0; ks < 32; ks += 16) {
            int pb = (ks >> 4) & 1;
            frag_a(pb, h_base, HSTM, kt * 32 + ks);
            frag_b(pb, wbuf, ks);
            MMA_STEP(pb)
        }
    }

    if (!out_final) {
        int rl = wm * 16 + gq;
        size_t r = (size_t)(row0 + rl);
#pragma unroll
        for (int j = 0; j < 6; j++) {
            int c = wn * 48 + j * 8 + 2 * tq;
            outres[r * Cdim + c]           = acc[j][0] + b2[c]     + res[r * Cdim + c];
            outres[r * Cdim + c + 1]       = acc[j][1] + b2[c + 1] + res[r * Cdim + c + 1];
            outres[(r + 8) * Cdim + c]     = acc[j][2] + b2[c]     + res[(r + 8) * Cdim + c];
            outres[(r + 8) * Cdim + c + 1] = acc[j][3] + b2[c + 1] + res[(r + 8) * Cdim + c + 1];
        }
    } else {
        float* stage = (float*)hid;
        __syncthreads();
        {
            int rl = wm * 16 + gq;
            size_t r = (size_t)(row0 + rl);
#pragma unroll
            for (int j = 0; j < 6; j++) {
                int c = wn * 48 + j * 8 + 2 * tq;
                stage[rl * 193 + c]           = acc[j][0] + b2[c]     + res[r * Cdim + c];
                stage[rl * 193 + c + 1]       = acc[j][1] + b2[c + 1] + res[r * Cdim + c + 1];
                stage[(rl + 8) * 193 + c]     = acc[j][2] + b2[c]     + res[(r + 8) * Cdim + c];
                stage[(rl + 8) * 193 + c + 1] = acc[j][3] + b2[c + 1] + res[(r + 8) * Cdim + c + 1];
            }
        }
        __syncthreads();
        int sfr = row0 >> 10;
        int hw0l = row0 & 1023;
#pragma unroll
        for (int i = 0; i < 24; i++) {
            int idx = tid + i * 512;
            int c = idx >> 6, hwl = idx & 63;
            size_t xi = ((size_t)c * 8 + sfr) * 1024 + hw0l + hwl;
            out_final[xi] = xt[xi] + stage[hwl * 193 + c];
        }
    }
#undef MMA_STEP
}

// ---------------- time attention ----------------
__global__ void time_attn_kernel() {
    int n = blockIdx.x;
    int h = threadIdx.x >> 5, lane = threadIdx.x & 31;
    const bf16* base = g_qkvb + (size_t)n * 8 * (3 * Cdim);
    float kreg[8], vreg[8];
#pragma unroll
    for (int j = 0; j < 8; j++) {
        kreg[j] = __bfloat162float(base[j * 576 + Cdim + h * 32 + lane]);
        vreg[j] = __bfloat162float(base[j * 576 + 2 * Cdim + h * 32 + lane]);
    }
#pragma unroll
    for (int s = 0; s < 8; s++) {
        float qv = __bfloat162float(base[s * 576 + h * 32 + lane]);
        float sc[8];
#pragma unroll
        for (int j = 0; j < 8; j++) sc[j] = warp_sum(qv * kreg[j]) * SCALE;
        float mx = sc[0];
#pragma unroll
        for (int j = 1; j < 8; j++) mx = fmaxf(mx, sc[j]);
        float sum = 0.f, o = 0.f;
#pragma unroll
        for (int j = 0; j < 8; j++) {
            float p = __expf(sc[j] - mx);
            sum += p;
            o += p * vreg[j];
        }
        g_ob[(size_t)(n * 8 + s) * Cdim + h * 32 + lane] = __float2bfloat16(o / sum);
    }
}

// ---------------- NAT attention ----------------
__global__ void nat_attn_kernel(const float* __restrict__ rpb) {
    int f = blockIdx.x >> 5;
    int hh = blockIdx.x & 31;
    int wno = threadIdx.x >> 5, lane = threadIdx.x & 31;
    int h = wno % NHEAD, half = wno / NHEAD;
    __shared__ float sc[12][52];
    int sh0 = min(max(hh - 3, 0), 25);
    int ww0 = half * 16;
    for (int ww = ww0; ww < ww0 + 16; ww++) {
        size_t m = (size_t)f * 1024 + hh * 32 + ww;
        float qv = __bfloat162float(g_qkvb[m * 576 + h * 32 + lane]) * SCALE;
        int sw0 = min(max(ww - 3, 0), 25);
#pragma unroll
        for (int a = 0; a < 7; a++) {
            int ia = sh0 + a;
            int rh = ia - hh + 6;
            const bf16* krow = g_qkvb + ((size_t)f * 1024 + ia * 32 + sw0) * 576 + Cdim + h * 32 + lane;
#pragma unroll
            for (int b = 0; b < 7; b++) {
                float d = warp_sum(qv * __bfloat162float(krow[b * 576]));
                if (lane == 0) {
                    int rw = sw0 + b - ww + 6;
                    sc[wno][a * 7 + b] = d + rpb[h * 169 + rh * 13 + rw];
                }
            }
        }
        __syncwarp();
        float mx = -1e30f;
#pragma unroll
        for (int n2 = 0; n2 < 49; n2++) mx = fmaxf(mx, sc[wno][n2]);
        float sum = 0.f, o = 0.f;
#pragma unroll
        for (int a = 0; a < 7; a++) {
            int ia = sh0 + a;
            const bf16* vrow = g_qkvb + ((size_t)f * 1024 + ia * 32 + sw0) * 576 + 2 * Cdim + h * 32 + lane;
#pragma unroll
            for (int b = 0; b < 7; b++) {
                float p = __expf(sc[wno][a * 7 + b] - mx);
                sum += p;
                o += p * __bfloat162float(vrow[b * 576]);
            }
        }
        g_ob[m * Cdim + h * 32 + lane] = __float2bfloat16(o / sum);
        __syncwarp();
    }
}

extern "C" void kernel_launch(void* const* d_in, const int* in_sizes, int n_in,
                              void* d_out, int out_size) {
    const float* x        = (const float*)d_in[0];
    const float* pos_emb  = (const float*)d_in[1];
    const float* t_ln1_g  = (const float*)d_in[2];
    const float* t_ln1_b  = (const float*)d_in[3];
    const float* t_qkv_w  = (const float*)d_in[4];
    const float* t_out_w  = (const float*)d_in[5];
    const float* t_out_b  = (const float*)d_in[6];
    const float* t_ln2_g  = (const float*)d_in[7];
    const float* t_ln2_b  = (const float*)d_in[8];
    const float* t_fc1_w  = (const float*)d_in[9];
    const float* t_fc1_b  = (const float*)d_in[10];
    const float* t_fc2_w  = (const float*)d_in[11];
    const float* t_fc2_b  = (const float*)d_in[12];
    const float* t_lnf_g  = (const float*)d_in[13];
    const float* t_lnf_b  = (const float*)d_in[14];
    const float* s_ln1_g  = (const float*)d_in[15];
    const float* s_ln1_b  = (const float*)d_in[16];
    const float* s_qkv_w  = (const float*)d_in[17];
    const float* s_qkv_b  = (const float*)d_in[18];
    const float* s_rpb    = (const float*)d_in[19];
    const float* s_proj_w = (const float*)d_in[20];
    const float* s_proj_b = (const float*)d_in[21];
    const float* s_ln2_g  = (const float*)d_in[22];
    const float* s_ln2_b  = (const float*)d_in[23];
    const float* s_fc1_w  = (const float*)d_in[24];
    const float* s_fc1_b  = (const float*)d_in[25];
    const float* s_fc2_w  = (const float*)d_in[26];
    const float* s_fc2_b  = (const float*)d_in[27];
    float* out = (float*)d_out;

    float *p_t, *p_s, *p_xt;
    bf16 *p_yb, *p_ob, *p_wb, *p_qkvb;
    cudaGetSymbolAddress((void**)&p_t, g_t);
    cudaGetSymbolAddress((void**)&p_s, g_s);
    cudaGetSymbolAddress((void**)&p_xt, g_xt);
    cudaGetSymbolAddress((void**)&p_yb, g_yb);
    cudaGetSymbolAddress((void**)&p_ob, g_ob);
    cudaGetSymbolAddress((void**)&p_wb, g_wb);
    cudaGetSymbolAddress((void**)&p_qkvb, g_qkvb);

    const int SMEM_LN = 3 * A_TILE_L * 2 + 3 * B_TILE_L * 2;
    cudaFuncSetAttribute(gemm_ln, cudaFuncAttributeMaxDynamicSharedMemorySize, SMEM_LN);
    cudaFuncSetAttribute(mlp_fused, cudaFuncAttributeMaxDynamicSharedMemorySize, SMEM_MLP);

    convert_build_kernel<<<256 + 3456, 256>>>(x, pos_emb, t_ln1_g, t_ln1_b,
                                              t_qkv_w, t_out_w, t_fc1_w, t_fc2_w,
                                              s_qkv_w, s_proj_w, s_fc1_w, s_fc2_w);

    // ======== time transformer ========
    gemm_bf16<<<dim3(9, 64), 256>>>(p_yb, p_wb + OFF_TQKV, nullptr, p_qkvb,
                                    NTOK, 576, Cdim);
    time_attn_kernel<<<1024, 192>>>();
    gemm_ln<<<128, 512, SMEM_LN>>>(p_ob, p_wb + OFF_TOUT, t_out_b, p_t,
                                   p_t, p_yb, t_ln2_g, t_ln2_b, Cdim);
    mlp_fused<<<128, 512, SMEM_MLP>>>(p_yb, p_wb + OFF_TFC1, t_fc1_b,
                                      p_wb + OFF_TFC2, t_fc2_b, p_t,
                                      p_t, nullptr, nullptr);
    lnf_add_kernel<<<dim3(8, 32), dim3(32, 8)>>>(x, t_lnf_g, t_lnf_b, s_ln1_g, s_ln1_b);

    // ======== space transformer (NAT) ========
    gemm_bf16<<<dim3(9, 64), 256>>>(p_yb, p_wb + OFF_SQKV, s_qkv_b, p_qkvb,
                                    NTOK, 576, Cdim);
    nat_attn_kernel<<<256, 384>>>(s_rpb);
    gemm_ln<<<128, 512, SMEM_LN>>>(p_ob, p_wb + OFF_SPROJ, s_proj_b, p_s,
                                   p_s, p_yb, s_ln2_g, s_ln2_b, Cdim);
    mlp_fused<<<128, 512, SMEM_MLP>>>(p_yb, p_wb + OFF_SFC1, s_fc1_b,
                                      p_wb + OFF_SFC2, s_fc2_b, p_s,
                                      nullptr, out, p_xt);
}

// round 16
// speedup vs baseline: 1.0500x; 1.0079x over previous
#include <cuda_runtime.h>
#include <cuda_bf16.h>
#include <stdint.h>
#include <math.h>

#define Cdim 192
#define Dn 8
#define Hn 32
#define Wn 32
#define NHEAD 6
#define HDIM 32
#define HIDN 768
#define NTOK 8192
#define SCALE 0.17677669529663687f

typedef __nv_bfloat16 bf16;

// ---------------- scratch ----------------
__device__ float g_xt[Cdim * Dn * Hn * Wn];
__device__ float g_s[NTOK * Cdim];
__device__ bf16  g_qkvb[NTOK * 3 * Cdim];
__device__ bf16  g_yb[NTOK * Cdim];
__device__ bf16  g_ob[NTOK * Cdim];
__device__ bf16  g_wb[884736];

#define OFF_TQKV 0
#define OFF_TOUT 110592
#define OFF_TFC1 147456
#define OFF_TFC2 294912
#define OFF_SQKV 442368
#define OFF_SPROJ 552960
#define OFF_SFC1 589824
#define OFF_SFC2 737280

__device__ __forceinline__ float warp_sum(float v) {
#pragma unroll
    for (int o = 16; o > 0; o >>= 1) v += __shfl_xor_sync(0xffffffffu, v, o);
    return v;
}

__device__ __forceinline__ void cp16(void* dst, const void* src) {
    unsigned d = (unsigned)__cvta_generic_to_shared(dst);
    asm volatile("cp.async.cg.shared.global [%0], [%1], 16;" :: "r"(d), "l"(src));
}

__device__ __forceinline__ float gelu_f(float v) {
    return 0.5f * v * (1.0f + erff(v * 0.7071067811865476f));
}

// ---------------- kernel 1: convert weights + build t(in g_s slot? no) --------
// We keep t residual only inside fused kernels now; build_ln writes g_s? No:
// time stream needs residual t for proj/mlp. Keep g_t via g_s reuse is unsafe;
// use a dedicated buffer: reuse g_xt? xt written later. Keep separate:
__device__ float g_t[NTOK * Cdim];

__global__ void convert_build_kernel(
    const float* __restrict__ x, const float* __restrict__ pe,
    const float* __restrict__ g, const float* __restrict__ b,
    const float* __restrict__ a0, const float* __restrict__ a1,
    const float* __restrict__ a2, const float* __restrict__ a3,
    const float* __restrict__ a4, const float* __restrict__ a5,
    const float* __restrict__ a6, const float* __restrict__ a7) {
    int blk = blockIdx.x;
    int tid = threadIdx.x;
    if (blk >= 256) {
        int i = (blk - 256) * 256 + tid;
        const float* src; int off;
        if      (i < 110592) { src = a0; off = 0; }
        else if (i < 147456) { src = a1; off = 110592; }
        else if (i < 294912) { src = a2; off = 147456; }
        else if (i < 442368) { src = a3; off = 294912; }
        else if (i < 552960) { src = a4; off = 442368; }
        else if (i < 589824) { src = a5; off = 552960; }
        else if (i < 737280) { src = a6; off = 589824; }
        else                 { src = a7; off = 737280; }
        g_wb[i] = __float2bfloat16(src[i - off]);
        return;
    }
    __shared__ float xsm[Cdim][33];
    int s = blk >> 5;
    int hw0 = (blk & 31) * 32;
    int tx = tid & 31, ty = tid >> 5;
    int warp = ty, lane = tx;

#pragma unroll
    for (int i = 0; i < 24; i++) {
        int c = ty + 8 * i;
        xsm[c][tx] = x[((size_t)c * 8 + s) * 1024 + hw0 + tx] + pe[s * Cdim + c];
    }
    __syncthreads();

#pragma unroll
    for (int i = 0; i < 4; i++) {
        int hwl = warp + 8 * i;
        size_t r = (size_t)(hw0 + hwl) * 8 + s;
        float v[6];
        float sum = 0.f;
#pragma unroll
        for (int j = 0; j < 6; j++) { v[j] = xsm[lane + 32 * j][hwl]; sum += v[j]; }
        sum = warp_sum(sum);
        float m = sum * (1.0f / Cdim);
        float var = 0.f;
#pragma unroll
        for (int j = 0; j < 6; j++) { float d = v[j] - m; var += d * d; }
        var = warp_sum(var) * (1.0f / Cdim);
        float rstd = rsqrtf(var + 1e-5f);
#pragma unroll
        for (int j = 0; j < 6; j++) {
            int c = lane + 32 * j;
            g_t[r * Cdim + c] = v[j];
            g_yb[r * Cdim + c] = __float2bfloat16((v[j] - m) * rstd * g[c] + b[c]);
        }
    }
}

#define AST 40
#define BST 72

// ============ wide GEMM: BM=128, BN=64, BK=32, 3-stage ring (qkv) ============
#define A_TILE (128 * AST)
#define B_TILE (32 * BST)
__global__ __launch_bounds__(256) void gemm_bf16(
    const bf16* __restrict__ A, const bf16* __restrict__ B,
    const float* __restrict__ bias, bf16* __restrict__ outb,
    int M, int N, int K) {
    __shared__ bf16 As[3][A_TILE];
    __shared__ bf16 Bs[3][B_TILE];
    const int tid = threadIdx.x;
    const int lane = tid & 31;
    const int wid = tid >> 5;
    const int wm = wid >> 1, wn = wid & 1;
    const int row0 = blockIdx.y * 128, col0 = blockIdx.x * 64;
    const int gq = lane >> 2, tq = lane & 3;

    const int lrow8 = (lane & 7) + 8 * ((lane >> 3) & 1);
    const int lcol8 = 8 * (lane >> 4);
    unsigned as_base = (unsigned)__cvta_generic_to_shared(&As[0][0]);
    unsigned bs_base = (unsigned)__cvta_generic_to_shared(&Bs[0][0]);

    float acc[2][4][4] = {};

    const int a_m = (tid >> 2), a_q = (tid & 3);
    const int b_k = (tid >> 3), b_q = (tid & 7);

    auto load_tile = [&](int buf, int k0) {
#pragma unroll
        for (int j = 0; j < 2; j++) {
            int m = a_m + j * 64;
            cp16(&As[buf][m * AST + a_q * 8], &A[(size_t)(row0 + m) * K + k0 + a_q * 8]);
        }
        cp16(&Bs[buf][b_k * BST + b_q * 8], &B[(size_t)(k0 + b_k) * N + col0 + b_q * 8]);
        asm volatile("cp.async.commit_group;");
    };

    unsigned af[2][2][4], bfr[2][4][2];
    auto load_frag = [&](int pb, unsigned abuf, unsigned bbuf, int ks) {
#pragma unroll
        for (int i = 0; i < 2; i++) {
            unsigned addr = abuf + (unsigned)(((wm * 32 + i * 16 + lrow8) * AST + ks + lcol8) * 2);
            asm volatile("ldmatrix.sync.aligned.m8n8.x4.shared.b16 {%0,%1,%2,%3}, [%4];"
                         : "=r"(af[pb][i][0]), "=r"(af[pb][i][1]),
                           "=r"(af[pb][i][2]), "=r"(af[pb][i][3])
                         : "r"(addr));
        }
#pragma unroll
        for (int jp = 0; jp < 2; jp++) {
            unsigned addr = bbuf + (unsigned)(((ks + lrow8) * BST + wn * 32 + jp * 16 + lcol8) * 2);
            asm volatile("ldmatrix.sync.aligned.m8n8.x4.trans.shared.b16 {%0,%1,%2,%3}, [%4];"
                         : "=r"(bfr[pb][jp * 2][0]), "=r"(bfr[pb][jp * 2][1]),
                           "=r"(bfr[pb][jp * 2 + 1][0]), "=r"(bfr[pb][jp * 2 + 1][1])
                         : "r"(addr));
        }
    };

    const int nk = K / 32;
    load_tile(0, 0);
    if (nk > 1) load_tile(1, 32);

    for (int it = 0; it < nk; it++) {
        if (it + 1 < nk) asm volatile("cp.async.wait_group 1;");
        else             asm volatile("cp.async.wait_group 0;");
        __syncthreads();
        if (it + 2 < nk) load_tile((it + 2) % 3, (it + 2) * 32);

        int buf = it % 3;
        unsigned abuf = as_base + buf * (A_TILE * 2);
        unsigned bbuf = bs_base + buf * (B_TILE * 2);
        load_frag(0, abuf, bbuf, 0);
#pragma unroll
        for (int ks = 0; ks < 2; ks++) {
            int pb = ks & 1;
            if (ks < 1) load_frag(pb ^ 1, abuf, bbuf, 16);
#pragma unroll
            for (int i = 0; i < 2; i++)
#pragma unroll
                for (int j = 0; j < 4; j++) {
                    asm volatile(
                        "mma.sync.aligned.m16n8k16.row.col.f32.bf16.bf16.f32 "
                        "{%0,%1,%2,%3}, {%4,%5,%6,%7}, {%8,%9}, {%0,%1,%2,%3};"
                        : "+f"(acc[i][j][0]), "+f"(acc[i][j][1]),
                          "+f"(acc[i][j][2]), "+f"(acc[i][j][3])
                        : "r"(af[pb][i][0]), "r"(af[pb][i][1]),
                          "r"(af[pb][i][2]), "r"(af[pb][i][3]),
                          "r"(bfr[pb][j][0]), "r"(bfr[pb][j][1]));
                }
        }
    }

#pragma unroll
    for (int i = 0; i < 2; i++) {
        int r = row0 + wm * 32 + i * 16 + gq;
#pragma unroll
        for (int j = 0; j < 4; j++) {
            int c = col0 + wn * 32 + j * 8 + 2 * tq;
            float v0 = acc[i][j][0], v1 = acc[i][j][1];
            float v2 = acc[i][j][2], v3 = acc[i][j][3];
            if (bias) {
                float b0 = bias[c], b1 = bias[c + 1];
                v0 += b0; v1 += b1; v2 += b0; v3 += b1;
            }
            outb[(size_t)r * N + c]           = __float2bfloat16(v0);
            outb[(size_t)r * N + c + 1]       = __float2bfloat16(v1);
            outb[(size_t)(r + 8) * N + c]     = __float2bfloat16(v2);
            outb[(size_t)(r + 8) * N + c + 1] = __float2bfloat16(v3);
        }
    }
}

// ============ attn_proj_ln: time attention + out_proj + ln2 (fused) ============
// grid 128, 512 threads. CTA owns 64 tokens = 8 complete time-attn groups.
#define ASTA 200
#define WSTA 200
#define W_TILE_A (32 * WSTA)
#define SM_WS_OFF_A (64 * ASTA)
#define SMEM_APL ((SM_WS_OFF_A + 3 * W_TILE_A) * 2)   // 64000 B (epi 49408 fits)
__global__ __launch_bounds__(512) void attn_proj_ln(
    const bf16* __restrict__ W, const float* __restrict__ bias,
    const float* __restrict__ res, float* __restrict__ outres,
    bf16* __restrict__ outln, const float* __restrict__ lng,
    const float* __restrict__ lnb) {
    extern __shared__ char smraw[];
    bf16* As = (bf16*)smraw;
    bf16* Ws = (bf16*)smraw + SM_WS_OFF_A;
    float* epi = (float*)smraw;
    const int tid = threadIdx.x;
    const int lane = tid & 31;
    const int wid = tid >> 5;
    const int wm = wid >> 2, wn = wid & 3;
    const int row0 = blockIdx.x * 64;
    const int n0 = row0 >> 3;
    const int gq = lane >> 2, tq = lane & 3;
    const int lrow8 = (lane & 7) + 8 * ((lane >> 3) & 1);
    const int lcol8 = 8 * (lane >> 4);
    unsigned a_base = (unsigned)__cvta_generic_to_shared(As);
    unsigned w_base = (unsigned)__cvta_generic_to_shared(Ws);

    auto load_w = [&](int stage, int k0) {
#pragma unroll
        for (int t = 0; t < 2; t++) {
            int idx = tid + t * 512;
            if (idx < 768) {
                int row = idx / 24, cc = (idx % 24) * 8;
                cp16(&Ws[stage * W_TILE_A + row * WSTA + cc],
                     &W[(size_t)(k0 + row) * Cdim + cc]);
            }
        }
        asm volatile("cp.async.commit_group;");
    };

    // prefetch W tiles 0,1 (overlaps attention compute)
    load_w(0, 0);
    load_w(1, 32);

    // ---- attention: 48 (n,head) pairs, 3 per warp ----
#pragma unroll
    for (int pp = 0; pp < 3; pp++) {
        int p = wid * 3 + pp;
        int nl = p / 6, h = p % 6;
        const bf16* base = g_qkvb + (size_t)(n0 + nl) * 8 * 576;
        float kreg[8], vreg[8];
#pragma unroll
        for (int j = 0; j < 8; j++) {
            kreg[j] = __bfloat162float(base[j * 576 + Cdim + h * 32 + lane]);
            vreg[j] = __bfloat162float(base[j * 576 + 2 * Cdim + h * 32 + lane]);
        }
#pragma unroll
        for (int s = 0; s < 8; s++) {
            float qv = __bfloat162float(base[s * 576 + h * 32 + lane]);
            float sc[8];
#pragma unroll
            for (int j = 0; j < 8; j++) sc[j] = warp_sum(qv * kreg[j]) * SCALE;
            float mx = sc[0];
#pragma unroll
            for (int j = 1; j < 8; j++) mx = fmaxf(mx, sc[j]);
            float sum = 0.f, o = 0.f;
#pragma unroll
            for (int j = 0; j < 8; j++) {
                float pj = __expf(sc[j] - mx);
                sum += pj;
                o += pj * vreg[j];
            }
            As[(nl * 8 + s) * ASTA + h * 32 + lane] = __float2bfloat16(o / sum);
        }
    }
    __syncthreads();

    // ---- GEMM: out64x192 = As(64x192) @ W(192x192), K=192 ----
    unsigned af[2][4], bfr[2][6][2];
    float acc[6][4] = {};
    for (int kt = 0; kt < 6; kt++) {
        if (kt + 1 < 6) asm volatile("cp.async.wait_group 1;");
        else            asm volatile("cp.async.wait_group 0;");
        __syncthreads();
        if (kt + 2 < 6) load_w((kt + 2) % 3, (kt + 2) * 32);
        unsigned wbuf = w_base + (kt % 3) * (W_TILE_A * 2);
#pragma unroll
        for (int ks = 0; ks < 32; ks += 16) {
            int pb = (ks >> 4) & 1;
            {
                unsigned addr = a_base + (unsigned)(((wm * 16 + lrow8) * ASTA + kt * 32 + ks + lcol8) * 2);
                asm volatile("ldmatrix.sync.aligned.m8n8.x4.shared.b16 {%0,%1,%2,%3}, [%4];"
                             : "=r"(af[pb][0]), "=r"(af[pb][1]),
                               "=r"(af[pb][2]), "=r"(af[pb][3])
                             : "r"(addr));
            }
#pragma unroll
            for (int jp = 0; jp < 3; jp++) {
                unsigned addr = wbuf + (unsigned)(((ks + lrow8) * WSTA + wn * 48 + jp * 16 + lcol8) * 2);
                asm volatile("ldmatrix.sync.aligned.m8n8.x4.trans.shared.b16 {%0,%1,%2,%3}, [%4];"
                             : "=r"(bfr[pb][jp * 2][0]), "=r"(bfr[pb][jp * 2][1]),
                               "=r"(bfr[pb][jp * 2 + 1][0]), "=r"(bfr[pb][jp * 2 + 1][1])
                             : "r"(addr));
            }
#pragma unroll
            for (int j = 0; j < 6; j++) {
                asm volatile(
                    "mma.sync.aligned.m16n8k16.row.col.f32.bf16.bf16.f32 "
                    "{%0,%1,%2,%3}, {%4,%5,%6,%7}, {%8,%9}, {%0,%1,%2,%3};"
                    : "+f"(acc[j][0]), "+f"(acc[j][1]),
                      "+f"(acc[j][2]), "+f"(acc[j][3])
                    : "r"(af[pb][0]), "r"(af[pb][1]),
                      "r"(af[pb][2]), "r"(af[pb][3]),
                      "r"(bfr[pb][j][0]), "r"(bfr[pb][j][1]));
            }
        }
    }
    __syncthreads();

    // epilogue: bias + residual -> epi; LN -> outres + outln
    {
        int rl = wm * 16 + gq;
        size_t r = (size_t)(row0 + rl);
#pragma unroll
        for (int j = 0; j < 6; j++) {
            int c = wn * 48 + j * 8 + 2 * tq;
            epi[rl * 193 + c]           = acc[j][0] + bias[c]     + res[r * Cdim + c];
            epi[rl * 193 + c + 1]       = acc[j][1] + bias[c + 1] + res[r * Cdim + c + 1];
            epi[(rl + 8) * 193 + c]     = acc[j][2] + bias[c]     + res[(r + 8) * Cdim + c];
            epi[(rl + 8) * 193 + c + 1] = acc[j][3] + bias[c + 1] + res[(r + 8) * Cdim + c + 1];
        }
    }
    __syncthreads();

#pragma unroll
    for (int rr = 0; rr < 4; rr++) {
        int rl = wid * 4 + rr;
        size_t r = (size_t)(row0 + rl);
        float v[6];
        float sum = 0.f;
#pragma unroll
        for (int j = 0; j < 6; j++) { v[j] = epi[rl * 193 + lane + 32 * j]; sum += v[j]; }
        sum = warp_sum(sum);
        float m = sum * (1.0f / Cdim);
        float var = 0.f;
#pragma unroll
        for (int j = 0; j < 6; j++) { float d = v[j] - m; var += d * d; }
        var = warp_sum(var) * (1.0f / Cdim);
        float rstd = rsqrtf(var + 1e-5f);
#pragma unroll
        for (int j = 0; j < 6; j++) {
            int c = lane + 32 * j;
            outres[r * Cdim + c] = v[j];
            outln[r * Cdim + c] = __float2bfloat16((v[j] - m) * rstd * lng[c] + lnb[c]);
        }
    }
}

// ============ fused GEMM+LN: BM=64, BN=192, 512 thr (space proj + s_ln2) =======
#define ASTL 40
#define BSTL 200
#define A_TILE_L (64 * ASTL)
#define B_TILE_L (32 * BSTL)
__global__ __launch_bounds__(512) void gemm_ln(
    const bf16* __restrict__ A, const bf16* __restrict__ B,
    const float* __restrict__ bias, const float* __restrict__ res,
    float* __restrict__ outres, bf16* __restrict__ outln,
    const float* __restrict__ lng, const float* __restrict__ lnb,
    int K) {
    extern __shared__ char smraw[];
    bf16* As = (bf16*)smraw;
    bf16* Bs = (bf16*)smraw + 3 * A_TILE_L;
    float* epi = (float*)smraw;
    const int tid = threadIdx.x;
    const int lane = tid & 31;
    const int wid = tid >> 5;
    const int wm = wid >> 2, wn = wid & 3;
    const int row0 = blockIdx.x * 64;
    const int gq = lane >> 2, tq = lane & 3;

    const int lrow8 = (lane & 7) + 8 * ((lane >> 3) & 1);
    const int lcol8 = 8 * (lane >> 4);
    unsigned as_base = (unsigned)__cvta_generic_to_shared(As);
    unsigned bs_base = (unsigned)__cvta_generic_to_shared(Bs);

    float acc[6][4] = {};

    auto load_tile = [&](int buf, int k0) {
#pragma unroll
        for (int t = 0; t < 2; t++) {
            int idx = tid + t * 512;
            if (idx < 256) {
                int am = idx >> 2, aq = idx & 3;
                cp16(&As[buf * A_TILE_L + am * ASTL + aq * 8],
                     &A[(size_t)(row0 + am) * K + k0 + aq * 8]);
            } else {
                int q = idx - 256;
                int br = q / 24, bc = q % 24;
                cp16(&Bs[buf * B_TILE_L + br * BSTL + bc * 8],
                     &B[(size_t)(k0 + br) * Cdim + bc * 8]);
            }
        }
        asm volatile("cp.async.commit_group;");
    };

    unsigned af[2][4], bfr[2][6][2];
    auto load_frag = [&](int pb, unsigned abuf, unsigned bbuf, int ks) {
        {
            unsigned addr = abuf + (unsigned)(((wm * 16 + lrow8) * ASTL + ks + lcol8) * 2);
            asm volatile("ldmatrix.sync.aligned.m8n8.x4.shared.b16 {%0,%1,%2,%3}, [%4];"
                         : "=r"(af[pb][0]), "=r"(af[pb][1]),
                           "=r"(af[pb][2]), "=r"(af[pb][3])
                         : "r"(addr));
        }
#pragma unroll
        for (int jp = 0; jp < 3; jp++) {
            unsigned addr = bbuf + (unsigned)(((ks + lrow8) * BSTL + wn * 48 + jp * 16 + lcol8) * 2);
            asm volatile("ldmatrix.sync.aligned.m8n8.x4.trans.shared.b16 {%0,%1,%2,%3}, [%4];"
                         : "=r"(bfr[pb][jp * 2][0]), "=r"(bfr[pb][jp * 2][1]),
                           "=r"(bfr[pb][jp * 2 + 1][0]), "=r"(bfr[pb][jp * 2 + 1][1])
                         : "r"(addr));
        }
    };

    const int nk = K / 32;
    load_tile(0, 0);
    if (nk > 1) load_tile(1, 32);

    for (int it = 0; it < nk; it++) {
        if (it + 1 < nk) asm volatile("cp.async.wait_group 1;");
        else             asm volatile("cp.async.wait_group 0;");
        __syncthreads();
        if (it + 2 < nk) load_tile((it + 2) % 3, (it + 2) * 32);

        int buf = it % 3;
        unsigned abuf = as_base + buf * (A_TILE_L * 2);
        unsigned bbuf = bs_base + buf * (B_TILE_L * 2);
        load_frag(0, abuf, bbuf, 0);
#pragma unroll
        for (int ks = 0; ks < 2; ks++) {
            int pb = ks & 1;
            if (ks < 1) load_frag(pb ^ 1, abuf, bbuf, 16);
#pragma unroll
            for (int j = 0; j < 6; j++) {
                asm volatile(
                    "mma.sync.aligned.m16n8k16.row.col.f32.bf16.bf16.f32 "
                    "{%0,%1,%2,%3}, {%4,%5,%6,%7}, {%8,%9}, {%0,%1,%2,%3};"
                    : "+f"(acc[j][0]), "+f"(acc[j][1]),
                      "+f"(acc[j][2]), "+f"(acc[j][3])
                    : "r"(af[pb][0]), "r"(af[pb][1]),
                      "r"(af[pb][2]), "r"(af[pb][3]),
                      "r"(bfr[pb][j][0]), "r"(bfr[pb][j][1]));
            }
        }
    }
    __syncthreads();

    {
        int rl = wm * 16 + gq;
        size_t r = (size_t)(row0 + rl);
#pragma unroll
        for (int j = 0; j < 6; j++) {
            int c = wn * 48 + j * 8 + 2 * tq;
            epi[rl * 193 + c]           = acc[j][0] + bias[c]     + res[r * Cdim + c];
            epi[rl * 193 + c + 1]       = acc[j][1] + bias[c + 1] + res[r * Cdim + c + 1];
            epi[(rl + 8) * 193 + c]     = acc[j][2] + bias[c]     + res[(r + 8) * Cdim + c];
            epi[(rl + 8) * 193 + c + 1] = acc[j][3] + bias[c + 1] + res[(r + 8) * Cdim + c + 1];
        }
    }
    __syncthreads();

#pragma unroll
    for (int rr = 0; rr < 4; rr++) {
        int rl = wid * 4 + rr;
        size_t r = (size_t)(row0 + rl);
        float v[6];
        float sum = 0.f;
#pragma unroll
        for (int j = 0; j < 6; j++) { v[j] = epi[rl * 193 + lane + 32 * j]; sum += v[j]; }
        sum = warp_sum(sum);
        float m = sum * (1.0f / Cdim);
        float var = 0.f;
#pragma unroll
        for (int j = 0; j < 6; j++) { float d = v[j] - m; var += d * d; }
        var = warp_sum(var) * (1.0f / Cdim);
        float rstd = rsqrtf(var + 1e-5f);
#pragma unroll
        for (int j = 0; j < 6; j++) {
            int c = lane + 32 * j;
            outres[r * Cdim + c] = v[j];
            outln[r * Cdim + c] = __float2bfloat16((v[j] - m) * rstd * lng[c] + lnb[c]);
        }
    }
}

// ============ fused MLP, 512 thr; modes: plain / final-add / lnf(time) =========
#define ASTM 200
#define HSTM 776
#define WSTM 200
#define W_TILE_M (32 * WSTM)
#define SM_A_OFF 0
#define SM_W_OFF (64 * ASTM)
#define SM_H_OFF (SM_W_OFF + 3 * W_TILE_M)
#define SMEM_MLP ((SM_H_OFF + 64 * HSTM) * 2)
__global__ __launch_bounds__(512, 1) void mlp_fused(
    const bf16* __restrict__ A, const bf16* __restrict__ W1,
    const float* __restrict__ b1, const bf16* __restrict__ W2,
    const float* __restrict__ b2, const float* __restrict__ res,
    float* __restrict__ outres, float* __restrict__ out_final,
    const float* __restrict__ xt,
    const float* __restrict__ lnf_g, const float* __restrict__ lnf_b,
    const float* __restrict__ s1_g, const float* __restrict__ s1_b,
    const float* __restrict__ x) {
    extern __shared__ char smraw[];
    bf16* sm = (bf16*)smraw;
    bf16* Asm = sm + SM_A_OFF;
    bf16* Ws  = sm + SM_W_OFF;
    bf16* hid = sm + SM_H_OFF;
    const int tid = threadIdx.x;
    const int lane = tid & 31;
    const int wid = tid >> 5;
    const int wm = wid >> 2, wn = wid & 3;
    const int row0 = blockIdx.x * 64;
    const int gq = lane >> 2, tq = lane & 3;

    const int lrow8 = (lane & 7) + 8 * ((lane >> 3) & 1);
    const int lcol8 = 8 * (lane >> 4);
    unsigned a_base = (unsigned)__cvta_generic_to_shared(Asm);
    unsigned w_base = (unsigned)__cvta_generic_to_shared(Ws);
    unsigned h_base = (unsigned)__cvta_generic_to_shared(hid);

#pragma unroll
    for (int i = 0; i < 3; i++) {
        int idx = tid + i * 512;
        int rr = idx / 24, ch = idx % 24;
        cp16(&Asm[rr * ASTM + ch * 8], &A[(size_t)(row0 + rr) * Cdim + ch * 8]);
    }
    asm volatile("cp.async.commit_group;");

    auto load_w1 = [&](int stage, int k0, int n0) {
#pragma unroll
        for (int t = 0; t < 2; t++) {
            int idx = tid + t * 512;
            if (idx < 768) {
                int row = idx / 24, cc = (idx % 24) * 8;
                cp16(&Ws[stage * W_TILE_M + row * WSTM + cc],
                     &W1[(size_t)(k0 + row) * HIDN + n0 + cc]);
            }
        }
        asm volatile("cp.async.commit_group;");
    };
    auto load_w2 = [&](int stage, int k0) {
#pragma unroll
        for (int t = 0; t < 2; t++) {
            int idx = tid + t * 512;
            if (idx < 768) {
                int row = idx / 24, cc = (idx % 24) * 8;
                cp16(&Ws[stage * W_TILE_M + row * WSTM + cc],
                     &W2[(size_t)(k0 + row) * Cdim + cc]);
            }
        }
        asm volatile("cp.async.commit_group;");
    };

    unsigned af[2][4], bfr[2][6][2];
    auto frag_a = [&](int pb, unsigned abase, int stride, int kcol) {
        unsigned addr = abase + (unsigned)(((wm * 16 + lrow8) * stride + kcol + lcol8) * 2);
        asm volatile("ldmatrix.sync.aligned.m8n8.x4.shared.b16 {%0,%1,%2,%3}, [%4];"
                     : "=r"(af[pb][0]), "=r"(af[pb][1]),
                       "=r"(af[pb][2]), "=r"(af[pb][3])
                     : "r"(addr));
    };
    auto frag_b = [&](int pb, unsigned wbuf, int ks) {
#pragma unroll
        for (int jp = 0; jp < 3; jp++) {
            unsigned addr = wbuf + (unsigned)(((ks + lrow8) * WSTM + wn * 48 + jp * 16 + lcol8) * 2);
            asm volatile("ldmatrix.sync.aligned.m8n8.x4.trans.shared.b16 {%0,%1,%2,%3}, [%4];"
                         : "=r"(bfr[pb][jp * 2][0]), "=r"(bfr[pb][jp * 2][1]),
                           "=r"(bfr[pb][jp * 2 + 1][0]), "=r"(bfr[pb][jp * 2 + 1][1])
                         : "r"(addr));
        }
    };

#define MMA_STEP(pb)                                                                   \
    _Pragma("unroll")                                                                  \
    for (int j = 0; j < 6; j++) {                                                      \
        asm volatile(                                                                  \
            "mma.sync.aligned.m16n8k16.row.col.f32.bf16.bf16.f32 "                     \
            "{%0,%1,%2,%3}, {%4,%5,%6,%7}, {%8,%9}, {%0,%1,%2,%3};"                    \
            : "+f"(acc[j][0]), "+f"(acc[j][1]),                                        \
              "+f"(acc[j][2]), "+f"(acc[j][3])                                         \
            : "r"(af[pb][0]), "r"(af[pb][1]),                                          \
              "r"(af[pb][2]), "r"(af[pb][3]),                                          \
              "r"(bfr[pb][j][0]), "r"(bfr[pb][j][1]));                                 \
    }

    // phase 1
    for (int nc = 0; nc < 4; nc++) {
        int n0 = nc * 192;
        load_w1(0, 0, n0);
        load_w1(1, 32, n0);
        float acc[6][4] = {};
        for (int kt = 0; kt < 6; kt++) {
            if (kt + 1 < 6) asm volatile("cp.async.wait_group 1;");
            else            asm volatile("cp.async.wait_group 0;");
            __syncthreads();
            if (kt + 2 < 6) load_w1((kt + 2) % 3, (kt + 2) * 32, n0);
            unsigned wbuf = w_base + (kt % 3) * (W_TILE_M * 2);
#pragma unroll
            for (int ks = 0; ks < 32; ks += 16) {
                int pb = (ks >> 4) & 1;
                frag_a(pb, a_base, ASTM, kt * 32 + ks);
                frag_b(pb, wbuf, ks);
                MMA_STEP(pb)
            }
        }
        {
            int rl = wm * 16 + gq;
#pragma unroll
            for (int j = 0; j < 6; j++) {
                int c = wn * 48 + j * 8 + 2 * tq;
                int gc = n0 + c;
                hid[rl * HSTM + gc]           = __float2bfloat16(gelu_f(acc[j][0] + b1[gc]));
                hid[rl * HSTM + gc + 1]       = __float2bfloat16(gelu_f(acc[j][1] + b1[gc + 1]));
                hid[(rl + 8) * HSTM + gc]     = __float2bfloat16(gelu_f(acc[j][2] + b1[gc]));
                hid[(rl + 8) * HSTM + gc + 1] = __float2bfloat16(gelu_f(acc[j][3] + b1[gc + 1]));
            }
        }
    }

    // phase 2
    load_w2(0, 0);
    load_w2(1, 32);
    float acc[6][4] = {};
    for (int kt = 0; kt < 24; kt++) {
        if (kt + 1 < 24) asm volatile("cp.async.wait_group 1;");
        else             asm volatile("cp.async.wait_group 0;");
        __syncthreads();
        if (kt + 2 < 24) load_w2((kt + 2) % 3, (kt + 2) * 32);
        unsigned wbuf = w_base + (kt % 3) * (W_TILE_M * 2);
#pragma unroll
        for (int ks = 0; ks < 32; ks += 16) {
            int pb = (ks >> 4) & 1;
            frag_a(pb, h_base, HSTM, kt * 32 + ks);
            frag_b(pb, wbuf, ks);
            MMA_STEP(pb)
        }
    }

    if (lnf_g) {
        // time-stream: stage t = acc + b2 + res; LNf; xt = x + y; s-stream + s_ln1
        float* stage = (float*)hid;
        __syncthreads();
        {
            int rl = wm * 16 + gq;
            size_t r = (size_t)(row0 + rl);
#pragma unroll
            for (int j = 0; j < 6; j++) {
                int c = wn * 48 + j * 8 + 2 * tq;
                stage[rl * 193 + c]           = acc[j][0] + b2[c]     + res[r * Cdim + c];
                stage[rl * 193 + c + 1]       = acc[j][1] + b2[c + 1] + res[r * Cdim + c + 1];
                stage[(rl + 8) * 193 + c]     = acc[j][2] + b2[c]     + res[(r + 8) * Cdim + c];
                stage[(rl + 8) * 193 + c + 1] = acc[j][3] + b2[c + 1] + res[(r + 8) * Cdim + c + 1];
            }
        }
        __syncthreads();
        // LNf in-place
#pragma unroll
        for (int rr = 0; rr < 4; rr++) {
            int rl = wid * 4 + rr;
            float v[6];
            float sum = 0.f;
#pragma unroll
            for (int j = 0; j < 6; j++) { v[j] = stage[rl * 193 + lane + 32 * j]; sum += v[j]; }
            sum = warp_sum(sum);
            float m = sum * (1.0f / Cdim);
            float var = 0.f;
#pragma unroll
            for (int j = 0; j < 6; j++) { float d = v[j] - m; var += d * d; }
            var = warp_sum(var) * (1.0f / Cdim);
            float rstd = rsqrtf(var + 1e-5f);
#pragma unroll
            for (int j = 0; j < 6; j++) {
                int c = lane + 32 * j;
                stage[rl * 193 + c] = (v[j] - m) * rstd * lnf_g[c] + lnf_b[c];
            }
        }
        __syncthreads();
        // xtv = x + y, write g_xt (x-layout), stage <- xtv
        int hw0 = row0 >> 3;
#pragma unroll
        for (int i = 0; i < 24; i++) {
            int idx = tid + i * 512;
            int hwl = idx & 7, s = (idx >> 3) & 7, c = idx >> 6;
            int rl = hwl * 8 + s;
            size_t xi = (size_t)c * 8192 + s * 1024 + hw0 + hwl;
            float xv = x[xi] + stage[rl * 193 + c];
            g_xt[xi] = xv;
            stage[rl * 193 + c] = xv;
        }
        __syncthreads();
        // s_ln1: write g_s (fp32) + g_yb (bf16 LN)
#pragma unroll
        for (int rr = 0; rr < 4; rr++) {
            int rl = wid * 4 + rr;
            int hwl = rl >> 3, s = rl & 7;
            size_t rs = (size_t)s * 1024 + hw0 + hwl;
            float v[6];
            float sum = 0.f;
#pragma unroll
            for (int j = 0; j < 6; j++) { v[j] = stage[rl * 193 + lane + 32 * j]; sum += v[j]; }
            sum = warp_sum(sum);
            float m = sum * (1.0f / Cdim);
            float var = 0.f;
#pragma unroll
            for (int j = 0; j < 6; j++) { float d = v[j] - m; var += d * d; }
            var = warp_sum(var) * (1.0f / Cdim);
            float rstd = rsqrtf(var + 1e-5f);
#pragma unroll
            for (int j = 0; j < 6; j++) {
                int c = lane + 32 * j;
                g_s[rs * Cdim + c] = v[j];
                g_yb[rs * Cdim + c] = __float2bfloat16((v[j] - m) * rstd * s1_g[c] + s1_b[c]);
            }
        }
    } else if (!out_final) {
        int rl = wm * 16 + gq;
        size_t r = (size_t)(row0 + rl);
#pragma unroll
        for (int j = 0; j < 6; j++) {
            int c = wn * 48 + j * 8 + 2 * tq;
            outres[r * Cdim + c]           = acc[j][0] + b2[c]     + res[r * Cdim + c];
            outres[r * Cdim + c + 1]       = acc[j][1] + b2[c + 1] + res[r * Cdim + c + 1];
            outres[(r + 8) * Cdim + c]     = acc[j][2] + b2[c]     + res[(r + 8) * Cdim + c];
            outres[(r + 8) * Cdim + c + 1] = acc[j][3] + b2[c + 1] + res[(r + 8) * Cdim + c + 1];
        }
    } else {
        float* stage = (float*)hid;
        __syncthreads();
        {
            int rl = wm * 16 + gq;
            size_t r = (size_t)(row0 + rl);
#pragma unroll
            for (int j = 0; j < 6; j++) {
                int c = wn * 48 + j * 8 + 2 * tq;
                stage[rl * 193 + c]           = acc[j][0] + b2[c]     + res[r * Cdim + c];
                stage[rl * 193 + c + 1]       = acc[j][1] + b2[c + 1] + res[r * Cdim + c + 1];
                stage[(rl + 8) * 193 + c]     = acc[j][2] + b2[c]     + res[(r + 8) * Cdim + c];
                stage[(rl + 8) * 193 + c + 1] = acc[j][3] + b2[c + 1] + res[(r + 8) * Cdim + c + 1];
            }
        }
        __syncthreads();
        int sfr = row0 >> 10;
        int hw0l = row0 & 1023;
#pragma unroll
        for (int i = 0; i < 24; i++) {
            int idx = tid + i * 512;
            int c = idx >> 6, hwl = idx & 63;
            size_t xi = ((size_t)c * 8 + sfr) * 1024 + hw0l + hwl;
            out_final[xi] = xt[xi] + stage[hwl * 193 + c];
        }
    }
#undef MMA_STEP
}

// ---------------- NAT attention ----------------
__global__ void nat_attn_kernel(const float* __restrict__ rpb) {
    int f = blockIdx.x >> 5;
    int hh = blockIdx.x & 31;
    int wno = threadIdx.x >> 5, lane = threadIdx.x & 31;
    int h = wno % NHEAD, half = wno / NHEAD;
    __shared__ float sc[12][52];
    int sh0 = min(max(hh - 3, 0), 25);
    int ww0 = half * 16;
    for (int ww = ww0; ww < ww0 + 16; ww++) {
        size_t m = (size_t)f * 1024 + hh * 32 + ww;
        float qv = __bfloat162float(g_qkvb[m * 576 + h * 32 + lane]) * SCALE;
        int sw0 = min(max(ww - 3, 0), 25);
#pragma unroll
        for (int a = 0; a < 7; a++) {
            int ia = sh0 + a;
            int rh = ia - hh + 6;
            const bf16* krow = g_qkvb + ((size_t)f * 1024 + ia * 32 + sw0) * 576 + Cdim + h * 32 + lane;
#pragma unroll
            for (int b = 0; b < 7; b++) {
                float d = warp_sum(qv * __bfloat162float(krow[b * 576]));
                if (lane == 0) {
                    int rw = sw0 + b - ww + 6;
                    sc[wno][a * 7 + b] = d + rpb[h * 169 + rh * 13 + rw];
                }
            }
        }
        __syncwarp();
        float mx = -1e30f;
#pragma unroll
        for (int n2 = 0; n2 < 49; n2++) mx = fmaxf(mx, sc[wno][n2]);
        float sum = 0.f, o = 0.f;
#pragma unroll
        for (int a = 0; a < 7; a++) {
            int ia = sh0 + a;
            const bf16* vrow = g_qkvb + ((size_t)f * 1024 + ia * 32 + sw0) * 576 + 2 * Cdim + h * 32 + lane;
#pragma unroll
            for (int b = 0; b < 7; b++) {
                float p = __expf(sc[wno][a * 7 + b] - mx);
                sum += p;
                o += p * __bfloat162float(vrow[b * 576]);
            }
        }
        g_ob[m * Cdim + h * 32 + lane] = __float2bfloat16(o / sum);
        __syncwarp();
    }
}

extern "C" void kernel_launch(void* const* d_in, const int* in_sizes, int n_in,
                              void* d_out, int out_size) {
    const float* x        = (const float*)d_in[0];
    const float* pos_emb  = (const float*)d_in[1];
    const float* t_ln1_g  = (const float*)d_in[2];
    const float* t_ln1_b  = (const float*)d_in[3];
    const float* t_qkv_w  = (const float*)d_in[4];
    const float* t_out_w  = (const float*)d_in[5];
    const float* t_out_b  = (const float*)d_in[6];
    const float* t_ln2_g  = (const float*)d_in[7];
    const float* t_ln2_b  = (const float*)d_in[8];
    const float* t_fc1_w  = (const float*)d_in[9];
    const float* t_fc1_b  = (const float*)d_in[10];
    const float* t_fc2_w  = (const float*)d_in[11];
    const float* t_fc2_b  = (const float*)d_in[12];
    const float* t_lnf_g  = (const float*)d_in[13];
    const float* t_lnf_b  = (const float*)d_in[14];
    const float* s_ln1_g  = (const float*)d_in[15];
    const float* s_ln1_b  = (const float*)d_in[16];
    const float* s_qkv_w  = (const float*)d_in[17];
    const float* s_qkv_b  = (const float*)d_in[18];
    const float* s_rpb    = (const float*)d_in[19];
    const float* s_proj_w = (const float*)d_in[20];
    const float* s_proj_b = (const float*)d_in[21];
    const float* s_ln2_g  = (const float*)d_in[22];
    const float* s_ln2_b  = (const float*)d_in[23];
    const float* s_fc1_w  = (const float*)d_in[24];
    const float* s_fc1_b  = (const float*)d_in[25];
    const float* s_fc2_w  = (const float*)d_in[26];
    const float* s_fc2_b  = (const float*)d_in[27];
    float* out = (float*)d_out;

    float *p_t, *p_s, *p_xt;
    bf16 *p_yb, *p_ob, *p_wb, *p_qkvb;
    cudaGetSymbolAddress((void**)&p_t, g_t);
    cudaGetSymbolAddress((void**)&p_s, g_s);
    cudaGetSymbolAddress((void**)&p_xt, g_xt);
    cudaGetSymbolAddress((void**)&p_yb, g_yb);
    cudaGetSymbolAddress((void**)&p_ob, g_ob);
    cudaGetSymbolAddress((void**)&p_wb, g_wb);
    cudaGetSymbolAddress((void**)&p_qkvb, g_qkvb);

    const int SMEM_LN = 3 * A_TILE_L * 2 + 3 * B_TILE_L * 2;
    cudaFuncSetAttribute(gemm_ln, cudaFuncAttributeMaxDynamicSharedMemorySize, SMEM_LN);
    cudaFuncSetAttribute(mlp_fused, cudaFuncAttributeMaxDynamicSharedMemorySize, SMEM_MLP);
    cudaFuncSetAttribute(attn_proj_ln, cudaFuncAttributeMaxDynamicSharedMemorySize, SMEM_APL);

    convert_build_kernel<<<256 + 3456, 256>>>(x, pos_emb, t_ln1_g, t_ln1_b,
                                              t_qkv_w, t_out_w, t_fc1_w, t_fc2_w,
                                              s_qkv_w, s_proj_w, s_fc1_w, s_fc2_w);

    // ======== time transformer ========
    gemm_bf16<<<dim3(9, 64), 256>>>(p_yb, p_wb + OFF_TQKV, nullptr, p_qkvb,
                                    NTOK, 576, Cdim);
    attn_proj_ln<<<128, 512, SMEM_APL>>>(p_wb + OFF_TOUT, t_out_b, p_t,
                                         p_t, p_yb, t_ln2_g, t_ln2_b);
    mlp_fused<<<128, 512, SMEM_MLP>>>(p_yb, p_wb + OFF_TFC1, t_fc1_b,
                                      p_wb + OFF_TFC2, t_fc2_b, p_t,
                                      nullptr, nullptr, nullptr,
                                      t_lnf_g, t_lnf_b, s_ln1_g, s_ln1_b, x);

    // ======== space transformer (NAT) ========
    gemm_bf16<<<dim3(9, 64), 256>>>(p_yb, p_wb + OFF_SQKV, s_qkv_b, p_qkvb,
                                    NTOK, 576, Cdim);
    nat_attn_kernel<<<256, 384>>>(s_rpb);
    gemm_ln<<<128, 512, SMEM_LN>>>(p_ob, p_wb + OFF_SPROJ, s_proj_b, p_s,
                                   p_s, p_yb, s_ln2_g, s_ln2_b, Cdim);
    mlp_fused<<<128, 512, SMEM_MLP>>>(p_yb, p_wb + OFF_SFC1, s_fc1_b,
                                      p_wb + OFF_SFC2, s_fc2_b, p_s,
                                      nullptr, out, p_xt,
                                      nullptr, nullptr, nullptr, nullptr, nullptr);
}